// round 1
// baseline (speedup 1.0000x reference)
#include <cuda_runtime.h>
#include <cuda_bf16.h>
#include <math.h>

#define BB 2
#define LL 2048
#define DD 512
#define HH 8
#define DHH 64
#define NLAYERS 3
#define D2 1024
#define MTOT (BB * LL)          // 4096 rows
#define EPS 1e-5f

// ---------------- scratch (device globals; no allocations allowed) ----------
__device__ float g_h  [MTOT * DD];       // ln output
__device__ float g_q  [MTOT * DD];
__device__ float g_k  [MTOT * DD];
__device__ float g_v  [MTOT * DD];
__device__ float g_ctx[MTOT * DD];
__device__ float g_ffn[MTOT * D2];
__device__ float g_scores[(size_t)BB * HH * LL * LL];   // 256 MB

// ---------------- LayerNorm: one block per row (D=512), 256 threads --------
__global__ __launch_bounds__(256)
void ln_kernel(const float* __restrict__ x, const float* __restrict__ g,
               const float* __restrict__ b, float* __restrict__ out) {
    int row = blockIdx.x;
    const float* xr = x + (size_t)row * DD;
    float*       orow = out + (size_t)row * DD;
    int t = threadIdx.x;
    float v0 = xr[t], v1 = xr[t + 256];
    float s  = v0 + v1;
    float sq = v0 * v0 + v1 * v1;

    __shared__ float red[8], red2[8];
    for (int o = 16; o > 0; o >>= 1) {
        s  += __shfl_down_sync(0xffffffffu, s,  o);
        sq += __shfl_down_sync(0xffffffffu, sq, o);
    }
    int warp = t >> 5, lane = t & 31;
    if (lane == 0) { red[warp] = s; red2[warp] = sq; }
    __syncthreads();
    __shared__ float s_mean, s_inv;
    if (t == 0) {
        float ts = 0.f, tq = 0.f;
        #pragma unroll
        for (int i = 0; i < 8; i++) { ts += red[i]; tq += red2[i]; }
        float mean = ts * (1.0f / DD);
        float var  = tq * (1.0f / DD) - mean * mean;
        s_mean = mean;
        s_inv  = rsqrtf(var + EPS);
    }
    __syncthreads();
    float mean = s_mean, inv = s_inv;
    orow[t]       = (v0 - mean) * inv * g[t]       + b[t];
    orow[t + 256] = (v1 - mean) * inv * g[t + 256] + b[t + 256];
}

// ---------------- Generic tiled SGEMM: C = A(MxK) @ W(KxN) + bias ----------
// BM=BN=64, BK=16, 256 threads, 4x4 micro-tile. Optional ReLU / residual add.
template <int RELU, int RES>
__global__ __launch_bounds__(256)
void gemm_kernel(const float* __restrict__ A, const float* __restrict__ W,
                 const float* __restrict__ bias, const float* __restrict__ res,
                 float* __restrict__ C, int M, int N, int K) {
    __shared__ float As[16][64];
    __shared__ float Bs[16][64];

    int tid = threadIdx.x;
    int tx = tid & 15, ty = tid >> 4;
    int rowBase = blockIdx.y * 64;
    int colBase = blockIdx.x * 64;

    float acc[4][4] = {};

    for (int k0 = 0; k0 < K; k0 += 16) {
        // load A tile 64x16 (float4 along K, scatter-transpose into As[k][m])
        {
            int idx = tid * 4;
            int r = idx >> 4, c = idx & 15;
            float4 a4 = *(const float4*)(A + (size_t)(rowBase + r) * K + k0 + c);
            As[c + 0][r] = a4.x; As[c + 1][r] = a4.y;
            As[c + 2][r] = a4.z; As[c + 3][r] = a4.w;
        }
        // load W tile 16x64 (coalesced float4 along N)
        {
            int idx = tid * 4;
            int r = idx >> 6, c = idx & 63;
            *(float4*)&Bs[r][c] = *(const float4*)(W + (size_t)(k0 + r) * N + colBase + c);
        }
        __syncthreads();
        #pragma unroll
        for (int k = 0; k < 16; k++) {
            float a[4], b[4];
            #pragma unroll
            for (int i = 0; i < 4; i++) a[i] = As[k][ty * 4 + i];
            #pragma unroll
            for (int j = 0; j < 4; j++) b[j] = Bs[k][tx * 4 + j];
            #pragma unroll
            for (int i = 0; i < 4; i++)
                #pragma unroll
                for (int j = 0; j < 4; j++)
                    acc[i][j] += a[i] * b[j];
        }
        __syncthreads();
    }

    int col = colBase + tx * 4;
    float4 bi = *(const float4*)(bias + col);
    #pragma unroll
    for (int i = 0; i < 4; i++) {
        int m = rowBase + ty * 4 + i;
        float4 o;
        o.x = acc[i][0] + bi.x; o.y = acc[i][1] + bi.y;
        o.z = acc[i][2] + bi.z; o.w = acc[i][3] + bi.w;
        if (RES) {
            float4 r4 = *(const float4*)(res + (size_t)m * N + col);
            o.x += r4.x; o.y += r4.y; o.z += r4.z; o.w += r4.w;
        }
        if (RELU) {
            o.x = fmaxf(o.x, 0.f); o.y = fmaxf(o.y, 0.f);
            o.z = fmaxf(o.z, 0.f); o.w = fmaxf(o.w, 0.f);
        }
        *(float4*)(C + (size_t)m * N + col) = o;
    }
}

// ---------------- Attention scores: S = scale * Q @ K^T per (b,h) ----------
__global__ __launch_bounds__(256)
void attn_score_kernel(const float* __restrict__ q, const float* __restrict__ kk,
                       float* __restrict__ scores) {
    int bh = blockIdx.z;
    int b = bh / HH, h = bh % HH;
    const float* qb = q  + (size_t)b * LL * DD + h * DHH;
    const float* kb = kk + (size_t)b * LL * DD + h * DHH;
    float* sc = scores + (size_t)bh * LL * LL;

    __shared__ float As[16][64];
    __shared__ float Bs[16][64];
    int tid = threadIdx.x;
    int tx = tid & 15, ty = tid >> 4;
    int rowBase = blockIdx.y * 64;
    int colBase = blockIdx.x * 64;

    float acc[4][4] = {};

    for (int k0 = 0; k0 < DHH; k0 += 16) {
        {
            int idx = tid * 4;
            int r = idx >> 4, c = idx & 15;
            float4 a4 = *(const float4*)(qb + (size_t)(rowBase + r) * DD + k0 + c);
            As[c + 0][r] = a4.x; As[c + 1][r] = a4.y;
            As[c + 2][r] = a4.z; As[c + 3][r] = a4.w;
        }
        {
            int idx = tid * 4;
            int r = idx >> 4, c = idx & 15;
            float4 b4 = *(const float4*)(kb + (size_t)(colBase + r) * DD + k0 + c);
            Bs[c + 0][r] = b4.x; Bs[c + 1][r] = b4.y;
            Bs[c + 2][r] = b4.z; Bs[c + 3][r] = b4.w;
        }
        __syncthreads();
        #pragma unroll
        for (int k = 0; k < 16; k++) {
            float a[4], bb[4];
            #pragma unroll
            for (int i = 0; i < 4; i++) a[i] = As[k][ty * 4 + i];
            #pragma unroll
            for (int j = 0; j < 4; j++) bb[j] = Bs[k][tx * 4 + j];
            #pragma unroll
            for (int i = 0; i < 4; i++)
                #pragma unroll
                for (int j = 0; j < 4; j++)
                    acc[i][j] += a[i] * bb[j];
        }
        __syncthreads();
    }

    const float scale = 0.125f;  // 1/sqrt(64)
    int col = colBase + tx * 4;
    #pragma unroll
    for (int i = 0; i < 4; i++) {
        int m = rowBase + ty * 4 + i;
        float4 o;
        o.x = acc[i][0] * scale; o.y = acc[i][1] * scale;
        o.z = acc[i][2] * scale; o.w = acc[i][3] * scale;
        *(float4*)(sc + (size_t)m * LL + col) = o;
    }
}

// ---------------- Row softmax over L=2048 with key mask --------------------
__global__ __launch_bounds__(256)
void softmax_kernel(float* __restrict__ scores, const unsigned char* __restrict__ mask) {
    size_t row = blockIdx.x;                 // B*H*L rows
    int b = (int)(row / ((size_t)HH * LL));
    float* s = scores + row * LL;
    const unsigned char* mrow = mask + (size_t)b * LL;
    int t = threadIdx.x;

    float v[8];
    float mx = -INFINITY;
    #pragma unroll
    for (int i = 0; i < 8; i++) {
        int j = t + i * 256;
        float x = mrow[j] ? -INFINITY : s[j];
        v[i] = x;
        mx = fmaxf(mx, x);
    }
    __shared__ float red[8];
    for (int o = 16; o > 0; o >>= 1) mx = fmaxf(mx, __shfl_down_sync(0xffffffffu, mx, o));
    int warp = t >> 5, lane = t & 31;
    if (lane == 0) red[warp] = mx;
    __syncthreads();
    __shared__ float s_mx, s_inv;
    if (t == 0) {
        float m = red[0];
        #pragma unroll
        for (int i = 1; i < 8; i++) m = fmaxf(m, red[i]);
        s_mx = m;
    }
    __syncthreads();
    mx = s_mx;
    float sum = 0.f;
    #pragma unroll
    for (int i = 0; i < 8; i++) {
        v[i] = __expf(v[i] - mx);   // exp(-inf) == 0
        sum += v[i];
    }
    for (int o = 16; o > 0; o >>= 1) sum += __shfl_down_sync(0xffffffffu, sum, o);
    if (lane == 0) red[warp] = sum;
    __syncthreads();
    if (t == 0) {
        float ts = 0.f;
        #pragma unroll
        for (int i = 0; i < 8; i++) ts += red[i];
        s_inv = 1.0f / ts;
    }
    __syncthreads();
    float inv = s_inv;
    #pragma unroll
    for (int i = 0; i < 8; i++) s[t + i * 256] = v[i] * inv;
}

// ---------------- ctx = attn @ V per (b,h): M=L, N=64, K=L -----------------
__global__ __launch_bounds__(256)
void attn_ctx_kernel(const float* __restrict__ scores, const float* __restrict__ v,
                     float* __restrict__ ctx) {
    int bh = blockIdx.z;
    int b = bh / HH, h = bh % HH;
    const float* sc = scores + (size_t)bh * LL * LL;
    const float* vb = v   + (size_t)b * LL * DD + h * DHH;
    float*       cb = ctx + (size_t)b * LL * DD + h * DHH;

    __shared__ float As[16][64];
    __shared__ float Bs[16][64];
    int tid = threadIdx.x;
    int tx = tid & 15, ty = tid >> 4;
    int rowBase = blockIdx.y * 64;

    float acc[4][4] = {};

    for (int k0 = 0; k0 < LL; k0 += 16) {
        {
            int idx = tid * 4;
            int r = idx >> 4, c = idx & 15;
            float4 a4 = *(const float4*)(sc + (size_t)(rowBase + r) * LL + k0 + c);
            As[c + 0][r] = a4.x; As[c + 1][r] = a4.y;
            As[c + 2][r] = a4.z; As[c + 3][r] = a4.w;
        }
        {
            int idx = tid * 4;
            int r = idx >> 6, c = idx & 63;
            *(float4*)&Bs[r][c] = *(const float4*)(vb + (size_t)(k0 + r) * DD + c);
        }
        __syncthreads();
        #pragma unroll
        for (int k = 0; k < 16; k++) {
            float a[4], bb[4];
            #pragma unroll
            for (int i = 0; i < 4; i++) a[i] = As[k][ty * 4 + i];
            #pragma unroll
            for (int j = 0; j < 4; j++) bb[j] = Bs[k][tx * 4 + j];
            #pragma unroll
            for (int i = 0; i < 4; i++)
                #pragma unroll
                for (int j = 0; j < 4; j++)
                    acc[i][j] += a[i] * bb[j];
        }
        __syncthreads();
    }

    int col = tx * 4;
    #pragma unroll
    for (int i = 0; i < 4; i++) {
        int m = rowBase + ty * 4 + i;
        float4 o;
        o.x = acc[i][0]; o.y = acc[i][1]; o.z = acc[i][2]; o.w = acc[i][3];
        *(float4*)(cb + (size_t)m * DD + col) = o;
    }
}

// ---------------------------------------------------------------------------
extern "C" void kernel_launch(void* const* d_in, const int* in_sizes, int n_in,
                              void* d_out, int out_size) {
    (void)in_sizes; (void)n_in; (void)out_size;
    const float* x_in  = (const float*)d_in[0];
    const unsigned char* mask = (const unsigned char*)d_in[1];
    const float* ln_ag = (const float*)d_in[2];
    const float* ln_ab = (const float*)d_in[3];
    const float* wq = (const float*)d_in[4];
    const float* bq = (const float*)d_in[5];
    const float* wk = (const float*)d_in[6];
    const float* bk = (const float*)d_in[7];
    const float* wv = (const float*)d_in[8];
    const float* bv = (const float*)d_in[9];
    const float* wo = (const float*)d_in[10];
    const float* bo = (const float*)d_in[11];
    const float* ln_fg = (const float*)d_in[12];
    const float* ln_fb = (const float*)d_in[13];
    const float* w1 = (const float*)d_in[14];
    const float* b1 = (const float*)d_in[15];
    const float* w2 = (const float*)d_in[16];
    const float* b2 = (const float*)d_in[17];

    float* x = (float*)d_out;   // residual stream lives in the output buffer

    float *ph, *pq, *pk, *pv, *pctx, *pffn, *psc;
    cudaGetSymbolAddress((void**)&ph,   g_h);
    cudaGetSymbolAddress((void**)&pq,   g_q);
    cudaGetSymbolAddress((void**)&pk,   g_k);
    cudaGetSymbolAddress((void**)&pv,   g_v);
    cudaGetSymbolAddress((void**)&pctx, g_ctx);
    cudaGetSymbolAddress((void**)&pffn, g_ffn);
    cudaGetSymbolAddress((void**)&psc,  g_scores);

    cudaMemcpyAsync(x, x_in, (size_t)MTOT * DD * sizeof(float),
                    cudaMemcpyDeviceToDevice, 0);

    dim3 blk(256);
    dim3 gemm512(DD / 64, MTOT / 64);     // (8, 64)
    dim3 gemm1024(D2 / 64, MTOT / 64);    // (16, 64)
    dim3 gsc(LL / 64, LL / 64, BB * HH);  // (32, 32, 16)
    dim3 gctx(1, LL / 64, BB * HH);       // (1, 32, 16)

    for (int l = 0; l < NLAYERS; l++) {
        const float* Wq = wq + (size_t)l * DD * DD;
        const float* Wk = wk + (size_t)l * DD * DD;
        const float* Wv = wv + (size_t)l * DD * DD;
        const float* Wo = wo + (size_t)l * DD * DD;
        const float* W1 = w1 + (size_t)l * DD * D2;
        const float* W2 = w2 + (size_t)l * D2 * DD;

        // ---- attention block ----
        ln_kernel<<<MTOT, blk>>>(x, ln_ag + l * DD, ln_ab + l * DD, ph);
        gemm_kernel<0, 0><<<gemm512, blk>>>(ph, Wq, bq + l * DD, nullptr, pq, MTOT, DD, DD);
        gemm_kernel<0, 0><<<gemm512, blk>>>(ph, Wk, bk + l * DD, nullptr, pk, MTOT, DD, DD);
        gemm_kernel<0, 0><<<gemm512, blk>>>(ph, Wv, bv + l * DD, nullptr, pv, MTOT, DD, DD);
        attn_score_kernel<<<gsc, blk>>>(pq, pk, psc);
        softmax_kernel<<<BB * HH * LL, blk>>>(psc, mask);
        attn_ctx_kernel<<<gctx, blk>>>(psc, pv, pctx);
        gemm_kernel<0, 1><<<gemm512, blk>>>(pctx, Wo, bo + l * DD, x, x, MTOT, DD, DD);

        // ---- FFN block ----
        ln_kernel<<<MTOT, blk>>>(x, ln_fg + l * DD, ln_fb + l * DD, ph);
        gemm_kernel<1, 0><<<gemm1024, blk>>>(ph, W1, b1 + l * D2, nullptr, pffn, MTOT, D2, DD);
        gemm_kernel<0, 1><<<gemm512, blk>>>(pffn, W2, b2 + l * DD, x, x, MTOT, DD, D2);
    }
}

// round 2
// speedup vs baseline: 2.1846x; 2.1846x over previous
#include <cuda_runtime.h>
#include <cuda_bf16.h>
#include <math.h>

#define BB 2
#define LL 2048
#define DD 512
#define HH 8
#define DHH 64
#define NLAYERS 3
#define D2 1024
#define MTOT (BB * LL)          // 4096 rows
#define EPS 1e-5f

// ---------------- scratch (device globals; no allocations allowed) ----------
__device__ float g_h  [MTOT * DD];
__device__ float g_q  [MTOT * DD];
__device__ float g_k  [MTOT * DD];
__device__ float g_v  [MTOT * DD];
__device__ float g_ctx[MTOT * DD];
__device__ float g_ffn[MTOT * D2];
__device__ float g_scores[(size_t)BB * HH * LL * LL];   // 256 MB

__device__ __forceinline__ unsigned f2tf(float f) {
    unsigned u;
    asm("cvt.rna.tf32.f32 %0, %1;" : "=r"(u) : "f"(f));
    return u;
}

// ---------------- LayerNorm: one block per row (D=512), 256 threads --------
__global__ __launch_bounds__(256)
void ln_kernel(const float* __restrict__ x, const float* __restrict__ g,
               const float* __restrict__ b, float* __restrict__ out) {
    int row = blockIdx.x;
    const float* xr = x + (size_t)row * DD;
    float*       orow = out + (size_t)row * DD;
    int t = threadIdx.x;
    float v0 = xr[t], v1 = xr[t + 256];
    float s  = v0 + v1;
    float sq = v0 * v0 + v1 * v1;

    __shared__ float red[8], red2[8];
    for (int o = 16; o > 0; o >>= 1) {
        s  += __shfl_down_sync(0xffffffffu, s,  o);
        sq += __shfl_down_sync(0xffffffffu, sq, o);
    }
    int warp = t >> 5, lane = t & 31;
    if (lane == 0) { red[warp] = s; red2[warp] = sq; }
    __syncthreads();
    __shared__ float s_mean, s_inv;
    if (t == 0) {
        float ts = 0.f, tq = 0.f;
        #pragma unroll
        for (int i = 0; i < 8; i++) { ts += red[i]; tq += red2[i]; }
        float mean = ts * (1.0f / DD);
        float var  = tq * (1.0f / DD) - mean * mean;
        s_mean = mean;
        s_inv  = rsqrtf(var + EPS);
    }
    __syncthreads();
    float mean = s_mean, inv = s_inv;
    orow[t]       = (v0 - mean) * inv * g[t]       + b[t];
    orow[t + 256] = (v1 - mean) * inv * g[t + 256] + b[t + 256];
}

// ---------------- Row softmax over L=2048 with key mask --------------------
__global__ __launch_bounds__(256)
void softmax_kernel(float* __restrict__ scores, const unsigned char* __restrict__ mask) {
    size_t row = blockIdx.x;                 // B*H*L rows
    int b = (int)(row / ((size_t)HH * LL));
    float* s = scores + row * LL;
    const unsigned char* mrow = mask + (size_t)b * LL;
    int t = threadIdx.x;

    float v[8];
    float mx = -INFINITY;
    #pragma unroll
    for (int i = 0; i < 8; i++) {
        int j = t + i * 256;
        float x = mrow[j] ? -INFINITY : s[j];
        v[i] = x;
        mx = fmaxf(mx, x);
    }
    __shared__ float red[8];
    for (int o = 16; o > 0; o >>= 1) mx = fmaxf(mx, __shfl_down_sync(0xffffffffu, mx, o));
    int warp = t >> 5, lane = t & 31;
    if (lane == 0) red[warp] = mx;
    __syncthreads();
    __shared__ float s_mx, s_inv;
    if (t == 0) {
        float m = red[0];
        #pragma unroll
        for (int i = 1; i < 8; i++) m = fmaxf(m, red[i]);
        s_mx = m;
    }
    __syncthreads();
    mx = s_mx;
    float sum = 0.f;
    #pragma unroll
    for (int i = 0; i < 8; i++) {
        v[i] = __expf(v[i] - mx);
        sum += v[i];
    }
    for (int o = 16; o > 0; o >>= 1) sum += __shfl_down_sync(0xffffffffu, sum, o);
    if (lane == 0) red[warp] = sum;
    __syncthreads();
    if (t == 0) {
        float ts = 0.f;
        #pragma unroll
        for (int i = 0; i < 8; i++) ts += red[i];
        s_inv = 1.0f / ts;
    }
    __syncthreads();
    float inv = s_inv;
    #pragma unroll
    for (int i = 0; i < 8; i++) s[t + i * 256] = v[i] * inv;
}

// ---------------- tf32 tensor-core GEMM ------------------------------------
// C[z] = op(A[z] @ B[z]) with optional scale, bias, residual-add, relu.
// A row-major MxK. If BT==0: B row-major KxN. If BT==1: B row-major NxK (A@B^T).
// Batched via blockIdx.z -> (zb = z/HH, zh = z%HH) with per-operand strides.
// CTA tile BM x BN x 16, 256 threads, warp tile WM x WN, double-buffered smem.
template<int BM, int BN, int WM, int WN, int BT, int RELU, int RES, int HB>
__global__ __launch_bounds__(256)
void mma_gemm(const float* __restrict__ A, int lda, long long aZb, long long aZh,
              const float* __restrict__ B, int ldb, long long bZb, long long bZh,
              const float* __restrict__ bias,
              const float* __restrict__ res,
              float* __restrict__ C, int ldc, long long cZb, long long cZh,
              int K, float scale)
{
    constexpr int BK  = 16;
    constexpr int SA  = BM + 8;            // stride ≡ 8 (mod 32) -> conflict-free frags
    constexpr int SB  = BN + 8;
    constexpr int NVA = (BM * BK) / (4 * 256);
    constexpr int NVB = (BK * BN) / (4 * 256);
    constexpr int MT  = WM / 16, NT = WN / 8;
    constexpr int WCOLS = BN / WN;

    __shared__ unsigned As[2][BK * SA];
    __shared__ unsigned Bs[2][BK * SB];

    const int tid  = threadIdx.x;
    const int lane = tid & 31;
    const int warp = tid >> 5;
    const int g    = lane >> 2, tg = lane & 3;
    const int wr   = warp / WCOLS, wc = warp % WCOLS;
    const int mW   = wr * WM, nW = wc * WN;

    const int zb = blockIdx.z / HH, zh = blockIdx.z % HH;
    const float* Ab  = A + zb * aZb + zh * aZh + (size_t)blockIdx.y * BM * lda;
    const float* Bbp = B + zb * bZb + zh * bZh +
                       (BT ? (size_t)blockIdx.x * BN * ldb : (size_t)blockIdx.x * BN);
    float* Cb = C + zb * cZb + zh * cZh + (size_t)blockIdx.y * BM * ldc +
                (size_t)blockIdx.x * BN;

    float acc[MT][NT][4];
    #pragma unroll
    for (int i = 0; i < MT; i++)
        #pragma unroll
        for (int j = 0; j < NT; j++)
            #pragma unroll
            for (int r = 0; r < 4; r++) acc[i][j][r] = 0.f;

    float4 aR[NVA], bR[NVB];

    // prologue: tile 0 directly to smem (convert to tf32 once per element)
    {
        #pragma unroll
        for (int i = 0; i < NVA; i++) {
            int v = tid * NVA + i; int r = v >> 2, kv = v & 3;
            float4 x = *(const float4*)(Ab + (size_t)r * lda + kv * 4);
            unsigned* d = &As[0][(kv * 4) * SA + r];
            d[0] = f2tf(x.x); d[SA] = f2tf(x.y); d[2*SA] = f2tf(x.z); d[3*SA] = f2tf(x.w);
        }
        #pragma unroll
        for (int i = 0; i < NVB; i++) {
            int v = tid * NVB + i;
            if (BT) {
                int n = v >> 2, kv = v & 3;
                float4 x = *(const float4*)(Bbp + (size_t)n * ldb + kv * 4);
                unsigned* d = &Bs[0][(kv * 4) * SB + n];
                d[0] = f2tf(x.x); d[SB] = f2tf(x.y); d[2*SB] = f2tf(x.z); d[3*SB] = f2tf(x.w);
            } else {
                int rk = v / (BN / 4), cv = v % (BN / 4);
                float4 x = *(const float4*)(Bbp + (size_t)rk * ldb + cv * 4);
                unsigned* d = &Bs[0][rk * SB + cv * 4];
                d[0] = f2tf(x.x); d[1] = f2tf(x.y); d[2] = f2tf(x.z); d[3] = f2tf(x.w);
            }
        }
    }
    __syncthreads();

    const int KT = K / BK;
    for (int kt = 0; kt < KT; kt++) {
        const int cur = kt & 1;
        if (kt + 1 < KT) {
            const int k0 = (kt + 1) * BK;
            #pragma unroll
            for (int i = 0; i < NVA; i++) {
                int v = tid * NVA + i; int r = v >> 2, kv = v & 3;
                aR[i] = *(const float4*)(Ab + (size_t)r * lda + k0 + kv * 4);
            }
            #pragma unroll
            for (int i = 0; i < NVB; i++) {
                int v = tid * NVB + i;
                if (BT) {
                    int n = v >> 2, kv = v & 3;
                    bR[i] = *(const float4*)(Bbp + (size_t)n * ldb + k0 + kv * 4);
                } else {
                    int rk = v / (BN / 4), cv = v % (BN / 4);
                    bR[i] = *(const float4*)(Bbp + (size_t)(k0 + rk) * ldb + cv * 4);
                }
            }
        }

        #pragma unroll
        for (int ks = 0; ks < 2; ks++) {
            const int kk = ks * 8;
            unsigned af[MT][4], bf[NT][2];
            #pragma unroll
            for (int mt = 0; mt < MT; mt++) {
                int m = mW + mt * 16;
                af[mt][0] = As[cur][(kk + tg)     * SA + m + g];
                af[mt][1] = As[cur][(kk + tg)     * SA + m + g + 8];
                af[mt][2] = As[cur][(kk + tg + 4) * SA + m + g];
                af[mt][3] = As[cur][(kk + tg + 4) * SA + m + g + 8];
            }
            #pragma unroll
            for (int nt = 0; nt < NT; nt++) {
                int n = nW + nt * 8;
                bf[nt][0] = Bs[cur][(kk + tg)     * SB + n + g];
                bf[nt][1] = Bs[cur][(kk + tg + 4) * SB + n + g];
            }
            #pragma unroll
            for (int mt = 0; mt < MT; mt++)
                #pragma unroll
                for (int nt = 0; nt < NT; nt++) {
                    asm volatile(
                        "mma.sync.aligned.m16n8k8.row.col.f32.tf32.tf32.f32 "
                        "{%0,%1,%2,%3}, {%4,%5,%6,%7}, {%8,%9}, {%0,%1,%2,%3};"
                        : "+f"(acc[mt][nt][0]), "+f"(acc[mt][nt][1]),
                          "+f"(acc[mt][nt][2]), "+f"(acc[mt][nt][3])
                        : "r"(af[mt][0]), "r"(af[mt][1]),
                          "r"(af[mt][2]), "r"(af[mt][3]),
                          "r"(bf[nt][0]), "r"(bf[nt][1]));
                }
        }

        if (kt + 1 < KT) {
            const int nxt = cur ^ 1;
            #pragma unroll
            for (int i = 0; i < NVA; i++) {
                int v = tid * NVA + i; int r = v >> 2, kv = v & 3;
                unsigned* d = &As[nxt][(kv * 4) * SA + r];
                d[0] = f2tf(aR[i].x); d[SA] = f2tf(aR[i].y);
                d[2*SA] = f2tf(aR[i].z); d[3*SA] = f2tf(aR[i].w);
            }
            #pragma unroll
            for (int i = 0; i < NVB; i++) {
                int v = tid * NVB + i;
                if (BT) {
                    int n = v >> 2, kv = v & 3;
                    unsigned* d = &Bs[nxt][(kv * 4) * SB + n];
                    d[0] = f2tf(bR[i].x); d[SB] = f2tf(bR[i].y);
                    d[2*SB] = f2tf(bR[i].z); d[3*SB] = f2tf(bR[i].w);
                } else {
                    int rk = v / (BN / 4), cv = v % (BN / 4);
                    unsigned* d = &Bs[nxt][rk * SB + cv * 4];
                    d[0] = f2tf(bR[i].x); d[1] = f2tf(bR[i].y);
                    d[2] = f2tf(bR[i].z); d[3] = f2tf(bR[i].w);
                }
            }
        }
        __syncthreads();
    }

    // epilogue
    #pragma unroll
    for (int mt = 0; mt < MT; mt++) {
        int r0 = mW + mt * 16 + g;
        #pragma unroll
        for (int nt = 0; nt < NT; nt++) {
            int c = nW + nt * 8 + 2 * tg;
            float2 o0, o1;
            o0.x = acc[mt][nt][0] * scale; o0.y = acc[mt][nt][1] * scale;
            o1.x = acc[mt][nt][2] * scale; o1.y = acc[mt][nt][3] * scale;
            if (HB) {
                float2 bi = *(const float2*)(bias + (size_t)blockIdx.x * BN + c);
                o0.x += bi.x; o0.y += bi.y; o1.x += bi.x; o1.y += bi.y;
            }
            if (RES) {
                const float* rb = res + (size_t)blockIdx.y * BM * ldc +
                                  (size_t)blockIdx.x * BN;
                float2 q0 = *(const float2*)(rb + (size_t)r0 * ldc + c);
                float2 q1 = *(const float2*)(rb + (size_t)(r0 + 8) * ldc + c);
                o0.x += q0.x; o0.y += q0.y; o1.x += q1.x; o1.y += q1.y;
            }
            if (RELU) {
                o0.x = fmaxf(o0.x, 0.f); o0.y = fmaxf(o0.y, 0.f);
                o1.x = fmaxf(o1.x, 0.f); o1.y = fmaxf(o1.y, 0.f);
            }
            *(float2*)(Cb + (size_t)r0 * ldc + c) = o0;
            *(float2*)(Cb + (size_t)(r0 + 8) * ldc + c) = o1;
        }
    }
}

// ---------------------------------------------------------------------------
extern "C" void kernel_launch(void* const* d_in, const int* in_sizes, int n_in,
                              void* d_out, int out_size) {
    (void)in_sizes; (void)n_in; (void)out_size;
    const float* x_in  = (const float*)d_in[0];
    const unsigned char* mask = (const unsigned char*)d_in[1];
    const float* ln_ag = (const float*)d_in[2];
    const float* ln_ab = (const float*)d_in[3];
    const float* wq = (const float*)d_in[4];
    const float* bq = (const float*)d_in[5];
    const float* wk = (const float*)d_in[6];
    const float* bk = (const float*)d_in[7];
    const float* wv = (const float*)d_in[8];
    const float* bv = (const float*)d_in[9];
    const float* wo = (const float*)d_in[10];
    const float* bo = (const float*)d_in[11];
    const float* ln_fg = (const float*)d_in[12];
    const float* ln_fb = (const float*)d_in[13];
    const float* w1 = (const float*)d_in[14];
    const float* b1 = (const float*)d_in[15];
    const float* w2 = (const float*)d_in[16];
    const float* b2 = (const float*)d_in[17];

    float* x = (float*)d_out;   // residual stream lives in the output buffer

    float *ph, *pq, *pk, *pv, *pctx, *pffn, *psc;
    cudaGetSymbolAddress((void**)&ph,   g_h);
    cudaGetSymbolAddress((void**)&pq,   g_q);
    cudaGetSymbolAddress((void**)&pk,   g_k);
    cudaGetSymbolAddress((void**)&pv,   g_v);
    cudaGetSymbolAddress((void**)&pctx, g_ctx);
    cudaGetSymbolAddress((void**)&pffn, g_ffn);
    cudaGetSymbolAddress((void**)&psc,  g_scores);

    cudaMemcpyAsync(x, x_in, (size_t)MTOT * DD * sizeof(float),
                    cudaMemcpyDeviceToDevice, 0);

    const long long sQb = (long long)LL * DD;   // per-batch stride in q/k/v/ctx
    const long long sQh = 64;                   // per-head stride
    const long long sSb = (long long)HH * LL * LL;
    const long long sSh = (long long)LL * LL;

    dim3 blk(256);
    dim3 gp(DD / 128, MTOT / 128, 1);     // (4, 32)
    dim3 g1(D2 / 128, MTOT / 128, 1);     // (8, 32)
    dim3 gsc(LL / 128, LL / 128, BB * HH);
    dim3 gcx(1, LL / 128, BB * HH);

    for (int l = 0; l < NLAYERS; l++) {
        const float* Wq = wq + (size_t)l * DD * DD;
        const float* Wk = wk + (size_t)l * DD * DD;
        const float* Wv = wv + (size_t)l * DD * DD;
        const float* Wo = wo + (size_t)l * DD * DD;
        const float* W1 = w1 + (size_t)l * DD * D2;
        const float* W2 = w2 + (size_t)l * D2 * DD;

        // ---- attention block ----
        ln_kernel<<<MTOT, blk>>>(x, ln_ag + l * DD, ln_ab + l * DD, ph);
        mma_gemm<128,128,64,32,0,0,0,1><<<gp, blk>>>(
            ph, DD, 0, 0, Wq, DD, 0, 0, bq + l * DD, nullptr, pq, DD, 0, 0, DD, 1.f);
        mma_gemm<128,128,64,32,0,0,0,1><<<gp, blk>>>(
            ph, DD, 0, 0, Wk, DD, 0, 0, bk + l * DD, nullptr, pk, DD, 0, 0, DD, 1.f);
        mma_gemm<128,128,64,32,0,0,0,1><<<gp, blk>>>(
            ph, DD, 0, 0, Wv, DD, 0, 0, bv + l * DD, nullptr, pv, DD, 0, 0, DD, 1.f);
        // S = 0.125 * Q @ K^T  per (b,h)
        mma_gemm<128,128,64,32,1,0,0,0><<<gsc, blk>>>(
            pq, DD, sQb, sQh, pk, DD, sQb, sQh, nullptr, nullptr,
            psc, LL, sSb, sSh, DHH, 0.125f);
        softmax_kernel<<<BB * HH * LL, blk>>>(psc, mask);
        // ctx = P @ V  per (b,h)
        mma_gemm<128,64,32,32,0,0,0,0><<<gcx, blk>>>(
            psc, LL, sSb, sSh, pv, DD, sQb, sQh, nullptr, nullptr,
            pctx, DD, sQb, sQh, LL, 1.f);
        mma_gemm<128,128,64,32,0,0,1,1><<<gp, blk>>>(
            pctx, DD, 0, 0, Wo, DD, 0, 0, bo + l * DD, x, x, DD, 0, 0, DD, 1.f);

        // ---- FFN block ----
        ln_kernel<<<MTOT, blk>>>(x, ln_fg + l * DD, ln_fb + l * DD, ph);
        mma_gemm<128,128,64,32,0,1,0,1><<<g1, blk>>>(
            ph, DD, 0, 0, W1, D2, 0, 0, b1 + l * D2, nullptr, pffn, D2, 0, 0, DD, 1.f);
        mma_gemm<128,128,64,32,0,0,1,1><<<gp, blk>>>(
            pffn, D2, 0, 0, W2, DD, 0, 0, b2 + l * DD, x, x, DD, 0, 0, D2, 1.f);
    }
}

// round 3
// speedup vs baseline: 2.9389x; 1.3453x over previous
#include <cuda_runtime.h>
#include <cuda_bf16.h>
#include <math.h>

#define BB 2
#define LL 2048
#define DD 512
#define HH 8
#define DHH 64
#define NLAYERS 3
#define D2 1024
#define MTOT (BB * LL)          // 4096 rows
#define EPS 1e-5f

// ---------------- scratch (device globals; no allocations allowed) ----------
__device__ float g_h  [MTOT * DD];
__device__ float g_q  [MTOT * DD];
__device__ float g_k  [MTOT * DD];
__device__ float g_v  [MTOT * DD];
__device__ float g_ctx[MTOT * DD];
__device__ float g_ffn[MTOT * D2];

// mma.tf32 truncates fp32 operand mantissas in HW -> feed raw fp32 bits.
__device__ __forceinline__ void mma_tf32(float* c, const unsigned* a,
                                         unsigned b0, unsigned b1) {
    asm volatile(
        "mma.sync.aligned.m16n8k8.row.col.f32.tf32.tf32.f32 "
        "{%0,%1,%2,%3}, {%4,%5,%6,%7}, {%8,%9}, {%0,%1,%2,%3};"
        : "+f"(c[0]), "+f"(c[1]), "+f"(c[2]), "+f"(c[3])
        : "r"(a[0]), "r"(a[1]), "r"(a[2]), "r"(a[3]), "r"(b0), "r"(b1));
}

// ---------------- LayerNorm: one block per row (D=512), 256 threads --------
__global__ __launch_bounds__(256)
void ln_kernel(const float* __restrict__ x, const float* __restrict__ g,
               const float* __restrict__ b, float* __restrict__ out) {
    int row = blockIdx.x;
    const float* xr = x + (size_t)row * DD;
    float*       orow = out + (size_t)row * DD;
    int t = threadIdx.x;
    float v0 = xr[t], v1 = xr[t + 256];
    float s  = v0 + v1;
    float sq = v0 * v0 + v1 * v1;

    __shared__ float red[8], red2[8];
    for (int o = 16; o > 0; o >>= 1) {
        s  += __shfl_down_sync(0xffffffffu, s,  o);
        sq += __shfl_down_sync(0xffffffffu, sq, o);
    }
    int warp = t >> 5, lane = t & 31;
    if (lane == 0) { red[warp] = s; red2[warp] = sq; }
    __syncthreads();
    __shared__ float s_mean, s_inv;
    if (t == 0) {
        float ts = 0.f, tq = 0.f;
        #pragma unroll
        for (int i = 0; i < 8; i++) { ts += red[i]; tq += red2[i]; }
        float mean = ts * (1.0f / DD);
        float var  = tq * (1.0f / DD) - mean * mean;
        s_mean = mean;
        s_inv  = rsqrtf(var + EPS);
    }
    __syncthreads();
    float mean = s_mean, inv = s_inv;
    orow[t]       = (v0 - mean) * inv * g[t]       + b[t];
    orow[t + 256] = (v1 - mean) * inv * g[t + 256] + b[t + 256];
}

// ---------------- tf32 tensor-core dense GEMM ------------------------------
// C = op(A @ B) + bias [+res] [relu].  A row-major MxK, B row-major KxN.
// CTA tile BM x BN x 16, 256 threads, warp tile WM x WN, double-buffered smem.
template<int BM, int BN, int WM, int WN, int RELU, int RES>
__global__ __launch_bounds__(256)
void mma_gemm(const float* __restrict__ A, int lda,
              const float* __restrict__ B, int ldb,
              const float* __restrict__ bias,
              const float* __restrict__ res,
              float* __restrict__ C, int ldc, int K)
{
    constexpr int BK  = 16;
    constexpr int SA  = BM + 8;            // ≡8 mod 32 -> conflict-free frags
    constexpr int SB  = BN + 8;
    constexpr int NVA = (BM * BK) / (4 * 256);
    constexpr int NVB = (BK * BN) / (4 * 256);
    constexpr int MT  = WM / 16, NT = WN / 8;
    constexpr int WCOLS = BN / WN;

    __shared__ unsigned As[2][BK * SA];
    __shared__ unsigned Bs[2][BK * SB];

    const int tid  = threadIdx.x;
    const int lane = tid & 31;
    const int warp = tid >> 5;
    const int g    = lane >> 2, tg = lane & 3;
    const int wr   = warp / WCOLS, wc = warp % WCOLS;
    const int mW   = wr * WM, nW = wc * WN;

    const float* Ab  = A + (size_t)blockIdx.y * BM * lda;
    const float* Bbp = B + (size_t)blockIdx.x * BN;
    float* Cb = C + (size_t)blockIdx.y * BM * ldc + (size_t)blockIdx.x * BN;

    float acc[MT][NT][4];
    #pragma unroll
    for (int i = 0; i < MT; i++)
        #pragma unroll
        for (int j = 0; j < NT; j++)
            #pragma unroll
            for (int r = 0; r < 4; r++) acc[i][j][r] = 0.f;

    float4 aR[NVA], bR[NVB];

    {   // prologue: tile 0 (store raw fp32 bits; HW truncates to tf32)
        #pragma unroll
        for (int i = 0; i < NVA; i++) {
            int v = tid * NVA + i; int r = v >> 2, kv = v & 3;
            float4 x = *(const float4*)(Ab + (size_t)r * lda + kv * 4);
            unsigned* d = &As[0][(kv * 4) * SA + r];
            d[0] = __float_as_uint(x.x); d[SA]   = __float_as_uint(x.y);
            d[2*SA] = __float_as_uint(x.z); d[3*SA] = __float_as_uint(x.w);
        }
        #pragma unroll
        for (int i = 0; i < NVB; i++) {
            int v = tid * NVB + i;
            int rk = v / (BN / 4), cv = v % (BN / 4);
            float4 x = *(const float4*)(Bbp + (size_t)rk * ldb + cv * 4);
            unsigned* d = &Bs[0][rk * SB + cv * 4];
            d[0] = __float_as_uint(x.x); d[1] = __float_as_uint(x.y);
            d[2] = __float_as_uint(x.z); d[3] = __float_as_uint(x.w);
        }
    }
    __syncthreads();

    const int KT = K / BK;
    for (int kt = 0; kt < KT; kt++) {
        const int cur = kt & 1;
        if (kt + 1 < KT) {
            const int k0 = (kt + 1) * BK;
            #pragma unroll
            for (int i = 0; i < NVA; i++) {
                int v = tid * NVA + i; int r = v >> 2, kv = v & 3;
                aR[i] = *(const float4*)(Ab + (size_t)r * lda + k0 + kv * 4);
            }
            #pragma unroll
            for (int i = 0; i < NVB; i++) {
                int v = tid * NVB + i;
                int rk = v / (BN / 4), cv = v % (BN / 4);
                bR[i] = *(const float4*)(Bbp + (size_t)(k0 + rk) * ldb + cv * 4);
            }
        }

        #pragma unroll
        for (int ks = 0; ks < 2; ks++) {
            const int kk = ks * 8;
            unsigned af[MT][4], bf[NT][2];
            #pragma unroll
            for (int mt = 0; mt < MT; mt++) {
                int m = mW + mt * 16;
                af[mt][0] = As[cur][(kk + tg)     * SA + m + g];
                af[mt][1] = As[cur][(kk + tg)     * SA + m + g + 8];
                af[mt][2] = As[cur][(kk + tg + 4) * SA + m + g];
                af[mt][3] = As[cur][(kk + tg + 4) * SA + m + g + 8];
            }
            #pragma unroll
            for (int nt = 0; nt < NT; nt++) {
                int n = nW + nt * 8;
                bf[nt][0] = Bs[cur][(kk + tg)     * SB + n + g];
                bf[nt][1] = Bs[cur][(kk + tg + 4) * SB + n + g];
            }
            #pragma unroll
            for (int mt = 0; mt < MT; mt++)
                #pragma unroll
                for (int nt = 0; nt < NT; nt++)
                    mma_tf32(acc[mt][nt], af[mt], bf[nt][0], bf[nt][1]);
        }

        if (kt + 1 < KT) {
            const int nxt = cur ^ 1;
            #pragma unroll
            for (int i = 0; i < NVA; i++) {
                int v = tid * NVA + i; int r = v >> 2, kv = v & 3;
                unsigned* d = &As[nxt][(kv * 4) * SA + r];
                d[0] = __float_as_uint(aR[i].x); d[SA]   = __float_as_uint(aR[i].y);
                d[2*SA] = __float_as_uint(aR[i].z); d[3*SA] = __float_as_uint(aR[i].w);
            }
            #pragma unroll
            for (int i = 0; i < NVB; i++) {
                int v = tid * NVB + i;
                int rk = v / (BN / 4), cv = v % (BN / 4);
                unsigned* d = &Bs[nxt][rk * SB + cv * 4];
                d[0] = __float_as_uint(bR[i].x); d[1] = __float_as_uint(bR[i].y);
                d[2] = __float_as_uint(bR[i].z); d[3] = __float_as_uint(bR[i].w);
            }
        }
        __syncthreads();
    }

    // epilogue
    #pragma unroll
    for (int mt = 0; mt < MT; mt++) {
        int r0 = mW + mt * 16 + g;
        #pragma unroll
        for (int nt = 0; nt < NT; nt++) {
            int c = nW + nt * 8 + 2 * tg;
            float2 bi = *(const float2*)(bias + (size_t)blockIdx.x * BN + c);
            float2 o0, o1;
            o0.x = acc[mt][nt][0] + bi.x; o0.y = acc[mt][nt][1] + bi.y;
            o1.x = acc[mt][nt][2] + bi.x; o1.y = acc[mt][nt][3] + bi.y;
            if (RES) {
                const float* rb = res + (size_t)blockIdx.y * BM * ldc +
                                  (size_t)blockIdx.x * BN;
                float2 q0 = *(const float2*)(rb + (size_t)r0 * ldc + c);
                float2 q1 = *(const float2*)(rb + (size_t)(r0 + 8) * ldc + c);
                o0.x += q0.x; o0.y += q0.y; o1.x += q1.x; o1.y += q1.y;
            }
            if (RELU) {
                o0.x = fmaxf(o0.x, 0.f); o0.y = fmaxf(o0.y, 0.f);
                o1.x = fmaxf(o1.x, 0.f); o1.y = fmaxf(o1.y, 0.f);
            }
            *(float2*)(Cb + (size_t)r0 * ldc + c) = o0;
            *(float2*)(Cb + (size_t)(r0 + 8) * ldc + c) = o1;
        }
    }
}

// ---------------- Flash attention ------------------------------------------
// grid = (L/128 q-tiles, B*H). 256 threads, warp owns 16 q-rows.
// KV tiles of 64 keys, cp.async double-buffered. Online softmax, tf32 mma.
#define FQ_WORDS (128 * 68)
#define FK_WORDS (64 * 68)
#define FV_WORDS (64 * 72)
#define FLASH_SMEM ((FQ_WORDS + 2 * FK_WORDS + 2 * FV_WORDS + LL) * 4)

__global__ __launch_bounds__(256)
void flash_kernel(const float* __restrict__ q, const float* __restrict__ k,
                  const float* __restrict__ v,
                  const unsigned char* __restrict__ mask,
                  float* __restrict__ ctx)
{
    extern __shared__ unsigned fsm[];
    unsigned* Qs = fsm;                         // [128][68]
    unsigned* Ks = Qs + FQ_WORDS;               // [2][64][68]
    unsigned* Vs = Ks + 2 * FK_WORDS;           // [2][64][72]
    float*    Ms = (float*)(Vs + 2 * FV_WORDS); // [2048] 0 / -inf

    const int tid  = threadIdx.x;
    const int lane = tid & 31, warp = tid >> 5;
    const int g    = lane >> 2, tg = lane & 3;
    const int bh   = blockIdx.y;
    const int b    = bh >> 3, h = bh & 7;
    const int q0   = blockIdx.x * 128;
    const int mW   = warp * 16;

    const float* qb = q + ((size_t)b * LL + q0) * DD + h * DHH;
    const float* kb = k + (size_t)b * LL * DD + h * DHH;
    const float* vb = v + (size_t)b * LL * DD + h * DHH;

    auto loadKV = [&](int tile, int buf) {
        int key0 = tile * 64;
        unsigned* kd = Ks + buf * FK_WORDS;
        unsigned* vd = Vs + buf * FV_WORDS;
        #pragma unroll
        for (int i = 0; i < 4; i++) {
            int idx = tid + i * 256;
            int row = idx >> 4, c4 = idx & 15;
            const float* sk = kb + (size_t)(key0 + row) * DD + c4 * 4;
            const float* sv = vb + (size_t)(key0 + row) * DD + c4 * 4;
            unsigned dk = (unsigned)__cvta_generic_to_shared(kd + row * 68 + c4 * 4);
            unsigned dv = (unsigned)__cvta_generic_to_shared(vd + row * 72 + c4 * 4);
            asm volatile("cp.async.cg.shared.global [%0], [%1], 16;" :: "r"(dk), "l"(sk));
            asm volatile("cp.async.cg.shared.global [%0], [%1], 16;" :: "r"(dv), "l"(sv));
        }
        asm volatile("cp.async.commit_group;");
    };

    loadKV(0, 0);
    loadKV(1, 1);

    // Q tile -> smem (raw bits), mask -> smem
    #pragma unroll
    for (int i = 0; i < 8; i++) {
        int idx = tid + i * 256;
        int row = idx >> 4, c4 = idx & 15;
        float4 x = *(const float4*)(qb + (size_t)row * DD + c4 * 4);
        unsigned* d = Qs + row * 68 + c4 * 4;
        d[0] = __float_as_uint(x.x); d[1] = __float_as_uint(x.y);
        d[2] = __float_as_uint(x.z); d[3] = __float_as_uint(x.w);
    }
    const unsigned char* mrow = mask + (size_t)b * LL;
    #pragma unroll
    for (int i = 0; i < 8; i++) {
        int idx = tid + i * 256;
        Ms[idx] = mrow[idx] ? -INFINITY : 0.f;
    }
    __syncthreads();

    // Q fragments live in registers for the whole kernel
    unsigned qf[8][4];
    #pragma unroll
    for (int kg = 0; kg < 8; kg++) {
        qf[kg][0] = Qs[(mW + g)     * 68 + 8 * kg + tg];
        qf[kg][1] = Qs[(mW + g + 8) * 68 + 8 * kg + tg];
        qf[kg][2] = Qs[(mW + g)     * 68 + 8 * kg + tg + 4];
        qf[kg][3] = Qs[(mW + g + 8) * 68 + 8 * kg + tg + 4];
    }

    float m0 = -1e30f, m1 = -1e30f, l0 = 0.f, l1 = 0.f;
    float o[8][4];
    #pragma unroll
    for (int nt = 0; nt < 8; nt++)
        #pragma unroll
        for (int j = 0; j < 4; j++) o[nt][j] = 0.f;

    const int srcA = (lane & ~3) | (tg >> 1);
    const int srcB = srcA + 2;

    for (int t = 0; t < LL / 64; t++) {
        const int buf = t & 1;
        if (t == LL / 64 - 1) asm volatile("cp.async.wait_group 0;");
        else                  asm volatile("cp.async.wait_group 1;");
        __syncthreads();

        const unsigned* Kb = Ks + buf * FK_WORDS;
        const unsigned* Vb = Vs + buf * FV_WORDS;

        // S = Q @ K^T  (warp: 16 x 64)
        float s[8][4];
        #pragma unroll
        for (int nt = 0; nt < 8; nt++)
            #pragma unroll
            for (int j = 0; j < 4; j++) s[nt][j] = 0.f;
        #pragma unroll
        for (int kg = 0; kg < 8; kg++) {
            #pragma unroll
            for (int nt = 0; nt < 8; nt++) {
                unsigned b0 = Kb[(8 * nt + g) * 68 + 8 * kg + tg];
                unsigned b1 = Kb[(8 * nt + g) * 68 + 8 * kg + tg + 4];
                mma_tf32(s[nt], qf[kg], b0, b1);
            }
        }

        // scale + mask + online softmax
        const int key0 = t * 64;
        float rm0 = -INFINITY, rm1 = -INFINITY;
        #pragma unroll
        for (int nt = 0; nt < 8; nt++) {
            float ma = Ms[key0 + 8 * nt + 2 * tg];
            float mb = Ms[key0 + 8 * nt + 2 * tg + 1];
            s[nt][0] = s[nt][0] * 0.125f + ma;
            s[nt][1] = s[nt][1] * 0.125f + mb;
            s[nt][2] = s[nt][2] * 0.125f + ma;
            s[nt][3] = s[nt][3] * 0.125f + mb;
            rm0 = fmaxf(rm0, fmaxf(s[nt][0], s[nt][1]));
            rm1 = fmaxf(rm1, fmaxf(s[nt][2], s[nt][3]));
        }
        rm0 = fmaxf(rm0, __shfl_xor_sync(0xffffffffu, rm0, 1));
        rm0 = fmaxf(rm0, __shfl_xor_sync(0xffffffffu, rm0, 2));
        rm1 = fmaxf(rm1, __shfl_xor_sync(0xffffffffu, rm1, 1));
        rm1 = fmaxf(rm1, __shfl_xor_sync(0xffffffffu, rm1, 2));

        float mn0 = fmaxf(m0, rm0), mn1 = fmaxf(m1, rm1);
        float al0 = __expf(m0 - mn0), al1 = __expf(m1 - mn1);
        float sum0 = 0.f, sum1 = 0.f;
        #pragma unroll
        for (int nt = 0; nt < 8; nt++) {
            s[nt][0] = __expf(s[nt][0] - mn0);
            s[nt][1] = __expf(s[nt][1] - mn0);
            s[nt][2] = __expf(s[nt][2] - mn1);
            s[nt][3] = __expf(s[nt][3] - mn1);
            sum0 += s[nt][0] + s[nt][1];
            sum1 += s[nt][2] + s[nt][3];
        }
        sum0 += __shfl_xor_sync(0xffffffffu, sum0, 1);
        sum0 += __shfl_xor_sync(0xffffffffu, sum0, 2);
        sum1 += __shfl_xor_sync(0xffffffffu, sum1, 1);
        sum1 += __shfl_xor_sync(0xffffffffu, sum1, 2);
        l0 = l0 * al0 + sum0; l1 = l1 * al1 + sum1;
        m0 = mn0; m1 = mn1;
        #pragma unroll
        for (int nt = 0; nt < 8; nt++) {
            o[nt][0] *= al0; o[nt][1] *= al0;
            o[nt][2] *= al1; o[nt][3] *= al1;
        }

        // O += P @ V : shuffle P (accumulator layout) into A-fragment layout
        #pragma unroll
        for (int kg = 0; kg < 8; kg++) {
            float w0, w1;
            unsigned a[4];
            w0 = __shfl_sync(0xffffffffu, s[kg][0], srcA);
            w1 = __shfl_sync(0xffffffffu, s[kg][1], srcA);
            a[0] = __float_as_uint((tg & 1) ? w1 : w0);
            w0 = __shfl_sync(0xffffffffu, s[kg][2], srcA);
            w1 = __shfl_sync(0xffffffffu, s[kg][3], srcA);
            a[1] = __float_as_uint((tg & 1) ? w1 : w0);
            w0 = __shfl_sync(0xffffffffu, s[kg][0], srcB);
            w1 = __shfl_sync(0xffffffffu, s[kg][1], srcB);
            a[2] = __float_as_uint((tg & 1) ? w1 : w0);
            w0 = __shfl_sync(0xffffffffu, s[kg][2], srcB);
            w1 = __shfl_sync(0xffffffffu, s[kg][3], srcB);
            a[3] = __float_as_uint((tg & 1) ? w1 : w0);
            #pragma unroll
            for (int nt = 0; nt < 8; nt++) {
                unsigned b0 = Vb[(8 * kg + tg)     * 72 + 8 * nt + g];
                unsigned b1 = Vb[(8 * kg + tg + 4) * 72 + 8 * nt + g];
                mma_tf32(o[nt], a, b0, b1);
            }
        }
        __syncthreads();
        if (t + 2 < LL / 64) loadKV(t + 2, buf);
    }

    // normalize + write ctx
    float i0 = 1.f / l0, i1 = 1.f / l1;
    float* cb = ctx + ((size_t)b * LL + q0 + mW) * DD + h * DHH;
    #pragma unroll
    for (int nt = 0; nt < 8; nt++) {
        int c = 8 * nt + 2 * tg;
        float2 u0, u1;
        u0.x = o[nt][0] * i0; u0.y = o[nt][1] * i0;
        u1.x = o[nt][2] * i1; u1.y = o[nt][3] * i1;
        *(float2*)(cb + (size_t)g * DD + c) = u0;
        *(float2*)(cb + (size_t)(g + 8) * DD + c) = u1;
    }
}

// ---------------------------------------------------------------------------
extern "C" void kernel_launch(void* const* d_in, const int* in_sizes, int n_in,
                              void* d_out, int out_size) {
    (void)in_sizes; (void)n_in; (void)out_size;
    const float* x_in  = (const float*)d_in[0];
    const unsigned char* mask = (const unsigned char*)d_in[1];
    const float* ln_ag = (const float*)d_in[2];
    const float* ln_ab = (const float*)d_in[3];
    const float* wq = (const float*)d_in[4];
    const float* bq = (const float*)d_in[5];
    const float* wk = (const float*)d_in[6];
    const float* bk = (const float*)d_in[7];
    const float* wv = (const float*)d_in[8];
    const float* bv = (const float*)d_in[9];
    const float* wo = (const float*)d_in[10];
    const float* bo = (const float*)d_in[11];
    const float* ln_fg = (const float*)d_in[12];
    const float* ln_fb = (const float*)d_in[13];
    const float* w1 = (const float*)d_in[14];
    const float* b1 = (const float*)d_in[15];
    const float* w2 = (const float*)d_in[16];
    const float* b2 = (const float*)d_in[17];

    float* x = (float*)d_out;   // residual stream lives in the output buffer

    float *ph, *pq, *pk, *pv, *pctx, *pffn;
    cudaGetSymbolAddress((void**)&ph,   g_h);
    cudaGetSymbolAddress((void**)&pq,   g_q);
    cudaGetSymbolAddress((void**)&pk,   g_k);
    cudaGetSymbolAddress((void**)&pv,   g_v);
    cudaGetSymbolAddress((void**)&pctx, g_ctx);
    cudaGetSymbolAddress((void**)&pffn, g_ffn);

    cudaFuncSetAttribute(flash_kernel,
                         cudaFuncAttributeMaxDynamicSharedMemorySize, FLASH_SMEM);

    cudaMemcpyAsync(x, x_in, (size_t)MTOT * DD * sizeof(float),
                    cudaMemcpyDeviceToDevice, 0);

    dim3 blk(256);
    dim3 gp(DD / 128, MTOT / 64);     // (4, 64)  projections / ffn2
    dim3 g1(D2 / 128, MTOT / 64);     // (8, 64)  ffn1
    dim3 gfl(LL / 128, BB * HH);      // (16, 16) flash

    for (int l = 0; l < NLAYERS; l++) {
        const float* Wq = wq + (size_t)l * DD * DD;
        const float* Wk = wk + (size_t)l * DD * DD;
        const float* Wv = wv + (size_t)l * DD * DD;
        const float* Wo = wo + (size_t)l * DD * DD;
        const float* W1 = w1 + (size_t)l * DD * D2;
        const float* W2 = w2 + (size_t)l * D2 * DD;

        // ---- attention block ----
        ln_kernel<<<MTOT, blk>>>(x, ln_ag + l * DD, ln_ab + l * DD, ph);
        mma_gemm<64,128,32,32,0,0><<<gp, blk>>>(ph, DD, Wq, DD, bq + l * DD, nullptr, pq, DD, DD);
        mma_gemm<64,128,32,32,0,0><<<gp, blk>>>(ph, DD, Wk, DD, bk + l * DD, nullptr, pk, DD, DD);
        mma_gemm<64,128,32,32,0,0><<<gp, blk>>>(ph, DD, Wv, DD, bv + l * DD, nullptr, pv, DD, DD);
        flash_kernel<<<gfl, blk, FLASH_SMEM>>>(pq, pk, pv, mask, pctx);
        mma_gemm<64,128,32,32,0,1><<<gp, blk>>>(pctx, DD, Wo, DD, bo + l * DD, x, x, DD, DD);

        // ---- FFN block ----
        ln_kernel<<<MTOT, blk>>>(x, ln_fg + l * DD, ln_fb + l * DD, ph);
        mma_gemm<64,128,32,32,1,0><<<g1, blk>>>(ph, DD, W1, D2, b1 + l * D2, nullptr, pffn, D2, DD);
        mma_gemm<64,128,32,32,0,1><<<gp, blk>>>(pffn, D2, W2, DD, b2 + l * DD, x, x, DD, D2);
    }
}

// round 4
// speedup vs baseline: 3.3764x; 1.1489x over previous
#include <cuda_runtime.h>
#include <cuda_bf16.h>
#include <math.h>

#define BB 2
#define LL 2048
#define DD 512
#define HH 8
#define DHH 64
#define NLAYERS 3
#define D2 1024
#define MTOT (BB * LL)          // 4096 rows
#define EPS 1e-5f

// ---------------- scratch (device globals; no allocations allowed) ----------
__device__ float g_h  [MTOT * DD];
__device__ float g_q  [MTOT * DD];
__device__ float g_k  [MTOT * DD];
__device__ float g_v  [MTOT * DD];
__device__ float g_ctx[MTOT * DD];
__device__ float g_ffn[MTOT * D2];

// mma.tf32 truncates fp32 operand mantissas in HW -> feed raw fp32 bits.
__device__ __forceinline__ void mma_tf32(float* c, const unsigned* a,
                                         unsigned b0, unsigned b1) {
    asm volatile(
        "mma.sync.aligned.m16n8k8.row.col.f32.tf32.tf32.f32 "
        "{%0,%1,%2,%3}, {%4,%5,%6,%7}, {%8,%9}, {%0,%1,%2,%3};"
        : "+f"(c[0]), "+f"(c[1]), "+f"(c[2]), "+f"(c[3])
        : "r"(a[0]), "r"(a[1]), "r"(a[2]), "r"(a[3]), "r"(b0), "r"(b1));
}

__device__ __forceinline__ void ldsm4(unsigned* r, unsigned addr) {
    asm volatile("ldmatrix.sync.aligned.m8n8.x4.shared.b16 {%0,%1,%2,%3}, [%4];"
                 : "=r"(r[0]), "=r"(r[1]), "=r"(r[2]), "=r"(r[3]) : "r"(addr));
}

__device__ __forceinline__ unsigned sptr(const void* p) {
    return (unsigned)__cvta_generic_to_shared(p);
}

// ---------------- LayerNorm: one block per row (D=512), 256 threads --------
__global__ __launch_bounds__(256)
void ln_kernel(const float* __restrict__ x, const float* __restrict__ g,
               const float* __restrict__ b, float* __restrict__ out) {
    int row = blockIdx.x;
    const float* xr = x + (size_t)row * DD;
    float*       orow = out + (size_t)row * DD;
    int t = threadIdx.x;
    float v0 = xr[t], v1 = xr[t + 256];
    float s  = v0 + v1;
    float sq = v0 * v0 + v1 * v1;

    __shared__ float red[8], red2[8];
    for (int o = 16; o > 0; o >>= 1) {
        s  += __shfl_down_sync(0xffffffffu, s,  o);
        sq += __shfl_down_sync(0xffffffffu, sq, o);
    }
    int warp = t >> 5, lane = t & 31;
    if (lane == 0) { red[warp] = s; red2[warp] = sq; }
    __syncthreads();
    __shared__ float s_mean, s_inv;
    if (t == 0) {
        float ts = 0.f, tq = 0.f;
        #pragma unroll
        for (int i = 0; i < 8; i++) { ts += red[i]; tq += red2[i]; }
        float mean = ts * (1.0f / DD);
        float var  = tq * (1.0f / DD) - mean * mean;
        s_mean = mean;
        s_inv  = rsqrtf(var + EPS);
    }
    __syncthreads();
    float mean = s_mean, inv = s_inv;
    orow[t]       = (v0 - mean) * inv * g[t]       + b[t];
    orow[t + 256] = (v1 - mean) * inv * g[t + 256] + b[t + 256];
}

// ---------------- tf32 ldmatrix tensor-core GEMM ---------------------------
// C = A @ B + bias [+res] [relu].  A row-major MxK, B row-major KxN.
// CTA 64x128x32, 256 threads (8 warps of 32x32), double-buffered swizzled smem.
// A smem [m][32k], B smem [n][32k] (transposed at staging); chunk swizzle
// (c ^ row)&7 -> conflict-free STS.128 staging AND conflict-free ldmatrix.
#define GEMM_SMEM 49152
template<int RELU, int RES>
__global__ __launch_bounds__(256)
void mma_gemm(const float* __restrict__ A, int lda,
              const float* __restrict__ B, int ldb,
              const float* __restrict__ bias,
              const float* __restrict__ res,
              float* __restrict__ C, int ldc, int K)
{
    constexpr int BM = 64, BN = 128, BK = 32;
    extern __shared__ unsigned gsm[];
    unsigned* As = gsm;              // [2][64*32]
    unsigned* Bs = gsm + 2 * (BM * BK); // [2][128*32]

    const int tid  = threadIdx.x;
    const int lane = tid & 31, warp = tid >> 5;
    const int g    = lane >> 2, tg = lane & 3;
    const int sub  = lane >> 3, rr = lane & 7;
    const int mW   = (warp >> 2) * 32, nW = (warp & 3) * 32;

    const int rowBase = blockIdx.y * BM;
    const int colBase = blockIdx.x * BN;
    const float* Ab = A + (size_t)rowBase * lda;
    const float* Bb = B + colBase;
    float* Cb = C + (size_t)rowBase * ldc + colBase;

    // staging coords
    const int am = tid >> 3, ac = tid & 7;      // A: row m (+32), chunk c
    const int bn = tid & 127, kh = tid >> 7;    // B: col n, k-half

    // ldmatrix lane geometry
    const int aRow0 = mW + (sub & 1) * 8 + rr;      // + mt*16
    const int aClS  = sub >> 1;
    const int nRow0 = nW + (sub >> 1) * 8 + rr;     // + p*16
    const int bClS  = sub & 1;

    const unsigned aBase = sptr(As);
    const unsigned bBase = sptr(Bs);

    float acc[2][4][4];
    #pragma unroll
    for (int i = 0; i < 2; i++)
        #pragma unroll
        for (int j = 0; j < 4; j++)
            #pragma unroll
            for (int r = 0; r < 4; r++) acc[i][j][r] = 0.f;

    float4 aR[2]; float bRv[16];

    auto fetchA = [&](int k0) {
        #pragma unroll
        for (int e = 0; e < 2; e++)
            aR[e] = *(const float4*)(Ab + (size_t)(am + e * 32) * lda + k0 + ac * 4);
    };
    auto fetchB = [&](int k0) {
        #pragma unroll
        for (int j = 0; j < 16; j++)
            bRv[j] = Bb[(size_t)(k0 + kh * 16 + j) * ldb + bn];
    };
    auto stageA = [&](int buf) {
        #pragma unroll
        for (int e = 0; e < 2; e++) {
            int m = am + e * 32;
            unsigned* d = As + buf * (BM * BK) + (m * 8 + ((ac ^ m) & 7)) * 4;
            *(uint4*)d = *(uint4*)&aR[e];
        }
    };
    auto stageB = [&](int buf) {
        #pragma unroll
        for (int jj = 0; jj < 4; jj++) {
            int cl = kh * 4 + jj;
            uint4 u;
            u.x = __float_as_uint(bRv[4 * jj + 0]);
            u.y = __float_as_uint(bRv[4 * jj + 1]);
            u.z = __float_as_uint(bRv[4 * jj + 2]);
            u.w = __float_as_uint(bRv[4 * jj + 3]);
            unsigned* d = Bs + buf * (BN * BK) + (bn * 8 + ((cl ^ bn) & 7)) * 4;
            *(uint4*)d = u;
        }
    };

    fetchA(0); fetchB(0);
    stageA(0); stageB(0);
    __syncthreads();

    const int KT = K / BK;
    for (int kt = 0; kt < KT; kt++) {
        const int cur = kt & 1;
        if (kt + 1 < KT) { fetchA((kt + 1) * BK); fetchB((kt + 1) * BK); }

        const unsigned aB = aBase + cur * (BM * BK) * 4;
        const unsigned bB = bBase + cur * (BN * BK) * 4;
        #pragma unroll
        for (int ksi = 0; ksi < 4; ksi++) {
            const int clb = ksi * 2;
            unsigned af[2][4], bf[2][4];
            #pragma unroll
            for (int mt = 0; mt < 2; mt++) {
                int row = aRow0 + mt * 16;
                int cl  = clb + aClS;
                ldsm4(af[mt], aB + ((row * 8 + ((cl ^ row) & 7)) << 4));
            }
            #pragma unroll
            for (int p = 0; p < 2; p++) {
                int row = nRow0 + p * 16;
                int cl  = clb + bClS;
                ldsm4(bf[p], bB + ((row * 8 + ((cl ^ row) & 7)) << 4));
            }
            #pragma unroll
            for (int mt = 0; mt < 2; mt++)
                #pragma unroll
                for (int nt = 0; nt < 4; nt++)
                    mma_tf32(acc[mt][nt], af[mt],
                             bf[nt >> 1][(nt & 1) * 2], bf[nt >> 1][(nt & 1) * 2 + 1]);
        }

        if (kt + 1 < KT) { stageA(cur ^ 1); stageB(cur ^ 1); }
        __syncthreads();
    }

    // epilogue
    #pragma unroll
    for (int mt = 0; mt < 2; mt++) {
        int r0 = mW + mt * 16 + g;
        #pragma unroll
        for (int nt = 0; nt < 4; nt++) {
            int c = nW + nt * 8 + 2 * tg;
            float2 bi = *(const float2*)(bias + colBase + c);
            float2 o0, o1;
            o0.x = acc[mt][nt][0] + bi.x; o0.y = acc[mt][nt][1] + bi.y;
            o1.x = acc[mt][nt][2] + bi.x; o1.y = acc[mt][nt][3] + bi.y;
            if (RES) {
                const float* rb = res + (size_t)rowBase * ldc + colBase;
                float2 q0 = *(const float2*)(rb + (size_t)r0 * ldc + c);
                float2 q1 = *(const float2*)(rb + (size_t)(r0 + 8) * ldc + c);
                o0.x += q0.x; o0.y += q0.y; o1.x += q1.x; o1.y += q1.y;
            }
            if (RELU) {
                o0.x = fmaxf(o0.x, 0.f); o0.y = fmaxf(o0.y, 0.f);
                o1.x = fmaxf(o1.x, 0.f); o1.y = fmaxf(o1.y, 0.f);
            }
            *(float2*)(Cb + (size_t)r0 * ldc + c) = o0;
            *(float2*)(Cb + (size_t)(r0 + 8) * ldc + c) = o1;
        }
    }
}

// ---------------- Flash attention ------------------------------------------
// grid = (L/128 q-tiles, B*H). 256 threads, warp owns 16 q-rows.
// Q/K smem: swizzled [row][16 chunks] for ldmatrix fragments.
// KV tiles of 64 keys, cp.async double-buffered. Online softmax, tf32 mma.
#define FQ_WORDS (128 * 64)
#define FK_WORDS (64 * 64)
#define FV_WORDS (64 * 72)
#define FLASH_SMEM ((FQ_WORDS + 2 * FK_WORDS + 2 * FV_WORDS + LL) * 4)

__global__ __launch_bounds__(256)
void flash_kernel(const float* __restrict__ q, const float* __restrict__ k,
                  const float* __restrict__ v,
                  const unsigned char* __restrict__ mask,
                  float* __restrict__ ctx)
{
    extern __shared__ unsigned fsm[];
    unsigned* Qs = fsm;                         // [128][16 chunks] swizzled
    unsigned* Ks = Qs + FQ_WORDS;               // [2][64][16 chunks] swizzled
    unsigned* Vs = Ks + 2 * FK_WORDS;           // [2][64][72] plain
    float*    Ms = (float*)(Vs + 2 * FV_WORDS); // [2048] 0 / -inf

    const int tid  = threadIdx.x;
    const int lane = tid & 31, warp = tid >> 5;
    const int g    = lane >> 2, tg = lane & 3;
    const int sub  = lane >> 3, rr = lane & 7;
    const int bh   = blockIdx.y;
    const int b    = bh >> 3, h = bh & 7;
    const int q0   = blockIdx.x * 128;
    const int mW   = warp * 16;

    const float* qb = q + ((size_t)b * LL + q0) * DD + h * DHH;
    const float* kb = k + (size_t)b * LL * DD + h * DHH;
    const float* vb = v + (size_t)b * LL * DD + h * DHH;

    auto loadKV = [&](int tile, int buf) {
        int key0 = tile * 64;
        unsigned* kd = Ks + buf * FK_WORDS;
        unsigned* vd = Vs + buf * FV_WORDS;
        #pragma unroll
        for (int i = 0; i < 4; i++) {
            int idx = tid + i * 256;
            int row = idx >> 4, c = idx & 15;
            const float* sk = kb + (size_t)(key0 + row) * DD + c * 4;
            const float* sv = vb + (size_t)(key0 + row) * DD + c * 4;
            unsigned dk = sptr(kd + (row * 16 + ((c & 8) | ((c ^ row) & 7))) * 4);
            unsigned dv = sptr(vd + row * 72 + c * 4);
            asm volatile("cp.async.cg.shared.global [%0], [%1], 16;" :: "r"(dk), "l"(sk));
            asm volatile("cp.async.cg.shared.global [%0], [%1], 16;" :: "r"(dv), "l"(sv));
        }
        asm volatile("cp.async.commit_group;");
    };

    loadKV(0, 0);
    loadKV(1, 1);

    // Q tile -> swizzled smem (raw bits), mask -> smem
    #pragma unroll
    for (int i = 0; i < 8; i++) {
        int idx = tid + i * 256;
        int row = idx >> 4, c = idx & 15;
        float4 x = *(const float4*)(qb + (size_t)row * DD + c * 4);
        uint4 u;
        u.x = __float_as_uint(x.x); u.y = __float_as_uint(x.y);
        u.z = __float_as_uint(x.z); u.w = __float_as_uint(x.w);
        *(uint4*)(Qs + (row * 16 + ((c & 8) | ((c ^ row) & 7))) * 4) = u;
    }
    const unsigned char* mrow = mask + (size_t)b * LL;
    #pragma unroll
    for (int i = 0; i < 8; i++) {
        int idx = tid + i * 256;
        Ms[idx] = mrow[idx] ? -INFINITY : 0.f;
    }
    __syncthreads();

    // Q fragments live in registers for the whole kernel (ldmatrix)
    const unsigned qBase = sptr(Qs);
    unsigned qf[8][4];
    #pragma unroll
    for (int kg = 0; kg < 8; kg++) {
        int row = mW + (sub & 1) * 8 + rr;
        int cl  = 2 * kg + (sub >> 1);
        ldsm4(qf[kg], qBase + ((row * 16 + ((cl & 8) | ((cl ^ row) & 7))) << 4));
    }

    float m0 = -1e30f, m1 = -1e30f, l0 = 0.f, l1 = 0.f;
    float o[8][4];
    #pragma unroll
    for (int nt = 0; nt < 8; nt++)
        #pragma unroll
        for (int j = 0; j < 4; j++) o[nt][j] = 0.f;

    const int srcA = (lane & ~3) | (tg >> 1);
    const int srcB = srcA + 2;
    const unsigned kBase = sptr(Ks);

    for (int t = 0; t < LL / 64; t++) {
        const int buf = t & 1;
        if (t == LL / 64 - 1) asm volatile("cp.async.wait_group 0;");
        else                  asm volatile("cp.async.wait_group 1;");
        __syncthreads();

        const unsigned kB = kBase + buf * FK_WORDS * 4;
        const unsigned* Vb = Vs + buf * FV_WORDS;

        // S = Q @ K^T  (warp: 16 x 64) via ldmatrix K fragments
        float s[8][4];
        #pragma unroll
        for (int nt = 0; nt < 8; nt++)
            #pragma unroll
            for (int j = 0; j < 4; j++) s[nt][j] = 0.f;
        #pragma unroll
        for (int kg = 0; kg < 8; kg++) {
            unsigned kf[4][4];
            #pragma unroll
            for (int p = 0; p < 4; p++) {
                int row = 16 * p + (sub >> 1) * 8 + rr;
                int cl  = 2 * kg + (sub & 1);
                ldsm4(kf[p], kB + ((row * 16 + ((cl & 8) | ((cl ^ row) & 7))) << 4));
            }
            #pragma unroll
            for (int nt = 0; nt < 8; nt++)
                mma_tf32(s[nt], qf[kg],
                         kf[nt >> 1][(nt & 1) * 2], kf[nt >> 1][(nt & 1) * 2 + 1]);
        }

        // scale + mask + online softmax
        const int key0 = t * 64;
        float rm0 = -INFINITY, rm1 = -INFINITY;
        #pragma unroll
        for (int nt = 0; nt < 8; nt++) {
            float ma = Ms[key0 + 8 * nt + 2 * tg];
            float mb = Ms[key0 + 8 * nt + 2 * tg + 1];
            s[nt][0] = s[nt][0] * 0.125f + ma;
            s[nt][1] = s[nt][1] * 0.125f + mb;
            s[nt][2] = s[nt][2] * 0.125f + ma;
            s[nt][3] = s[nt][3] * 0.125f + mb;
            rm0 = fmaxf(rm0, fmaxf(s[nt][0], s[nt][1]));
            rm1 = fmaxf(rm1, fmaxf(s[nt][2], s[nt][3]));
        }
        rm0 = fmaxf(rm0, __shfl_xor_sync(0xffffffffu, rm0, 1));
        rm0 = fmaxf(rm0, __shfl_xor_sync(0xffffffffu, rm0, 2));
        rm1 = fmaxf(rm1, __shfl_xor_sync(0xffffffffu, rm1, 1));
        rm1 = fmaxf(rm1, __shfl_xor_sync(0xffffffffu, rm1, 2));

        float mn0 = fmaxf(m0, rm0), mn1 = fmaxf(m1, rm1);
        float al0 = __expf(m0 - mn0), al1 = __expf(m1 - mn1);
        float sum0 = 0.f, sum1 = 0.f;
        #pragma unroll
        for (int nt = 0; nt < 8; nt++) {
            s[nt][0] = __expf(s[nt][0] - mn0);
            s[nt][1] = __expf(s[nt][1] - mn0);
            s[nt][2] = __expf(s[nt][2] - mn1);
            s[nt][3] = __expf(s[nt][3] - mn1);
            sum0 += s[nt][0] + s[nt][1];
            sum1 += s[nt][2] + s[nt][3];
        }
        sum0 += __shfl_xor_sync(0xffffffffu, sum0, 1);
        sum0 += __shfl_xor_sync(0xffffffffu, sum0, 2);
        sum1 += __shfl_xor_sync(0xffffffffu, sum1, 1);
        sum1 += __shfl_xor_sync(0xffffffffu, sum1, 2);
        l0 = l0 * al0 + sum0; l1 = l1 * al1 + sum1;
        m0 = mn0; m1 = mn1;
        #pragma unroll
        for (int nt = 0; nt < 8; nt++) {
            o[nt][0] *= al0; o[nt][1] *= al0;
            o[nt][2] *= al1; o[nt][3] *= al1;
        }

        // O += P @ V : shuffle P (accumulator layout) into A-fragment layout
        #pragma unroll
        for (int kg = 0; kg < 8; kg++) {
            float w0, w1;
            unsigned a[4];
            w0 = __shfl_sync(0xffffffffu, s[kg][0], srcA);
            w1 = __shfl_sync(0xffffffffu, s[kg][1], srcA);
            a[0] = __float_as_uint((tg & 1) ? w1 : w0);
            w0 = __shfl_sync(0xffffffffu, s[kg][2], srcA);
            w1 = __shfl_sync(0xffffffffu, s[kg][3], srcA);
            a[1] = __float_as_uint((tg & 1) ? w1 : w0);
            w0 = __shfl_sync(0xffffffffu, s[kg][0], srcB);
            w1 = __shfl_sync(0xffffffffu, s[kg][1], srcB);
            a[2] = __float_as_uint((tg & 1) ? w1 : w0);
            w0 = __shfl_sync(0xffffffffu, s[kg][2], srcB);
            w1 = __shfl_sync(0xffffffffu, s[kg][3], srcB);
            a[3] = __float_as_uint((tg & 1) ? w1 : w0);
            #pragma unroll
            for (int nt = 0; nt < 8; nt++) {
                unsigned b0 = Vb[(8 * kg + tg)     * 72 + 8 * nt + g];
                unsigned b1 = Vb[(8 * kg + tg + 4) * 72 + 8 * nt + g];
                mma_tf32(o[nt], a, b0, b1);
            }
        }
        __syncthreads();
        if (t + 2 < LL / 64) loadKV(t + 2, buf);
    }

    // normalize + write ctx
    float i0 = 1.f / l0, i1 = 1.f / l1;
    float* cb = ctx + ((size_t)b * LL + q0 + mW) * DD + h * DHH;
    #pragma unroll
    for (int nt = 0; nt < 8; nt++) {
        int c = 8 * nt + 2 * tg;
        float2 u0, u1;
        u0.x = o[nt][0] * i0; u0.y = o[nt][1] * i0;
        u1.x = o[nt][2] * i1; u1.y = o[nt][3] * i1;
        *(float2*)(cb + (size_t)g * DD + c) = u0;
        *(float2*)(cb + (size_t)(g + 8) * DD + c) = u1;
    }
}

// ---------------------------------------------------------------------------
extern "C" void kernel_launch(void* const* d_in, const int* in_sizes, int n_in,
                              void* d_out, int out_size) {
    (void)in_sizes; (void)n_in; (void)out_size;
    const float* x_in  = (const float*)d_in[0];
    const unsigned char* mask = (const unsigned char*)d_in[1];
    const float* ln_ag = (const float*)d_in[2];
    const float* ln_ab = (const float*)d_in[3];
    const float* wq = (const float*)d_in[4];
    const float* bq = (const float*)d_in[5];
    const float* wk = (const float*)d_in[6];
    const float* bk = (const float*)d_in[7];
    const float* wv = (const float*)d_in[8];
    const float* bv = (const float*)d_in[9];
    const float* wo = (const float*)d_in[10];
    const float* bo = (const float*)d_in[11];
    const float* ln_fg = (const float*)d_in[12];
    const float* ln_fb = (const float*)d_in[13];
    const float* w1 = (const float*)d_in[14];
    const float* b1 = (const float*)d_in[15];
    const float* w2 = (const float*)d_in[16];
    const float* b2 = (const float*)d_in[17];

    float* x = (float*)d_out;   // residual stream lives in the output buffer

    float *ph, *pq, *pk, *pv, *pctx, *pffn;
    cudaGetSymbolAddress((void**)&ph,   g_h);
    cudaGetSymbolAddress((void**)&pq,   g_q);
    cudaGetSymbolAddress((void**)&pk,   g_k);
    cudaGetSymbolAddress((void**)&pv,   g_v);
    cudaGetSymbolAddress((void**)&pctx, g_ctx);
    cudaGetSymbolAddress((void**)&pffn, g_ffn);

    cudaFuncSetAttribute(flash_kernel,
                         cudaFuncAttributeMaxDynamicSharedMemorySize, FLASH_SMEM);
    cudaFuncSetAttribute(mma_gemm<0,0>,
                         cudaFuncAttributeMaxDynamicSharedMemorySize, GEMM_SMEM);
    cudaFuncSetAttribute(mma_gemm<0,1>,
                         cudaFuncAttributeMaxDynamicSharedMemorySize, GEMM_SMEM);
    cudaFuncSetAttribute(mma_gemm<1,0>,
                         cudaFuncAttributeMaxDynamicSharedMemorySize, GEMM_SMEM);

    cudaMemcpyAsync(x, x_in, (size_t)MTOT * DD * sizeof(float),
                    cudaMemcpyDeviceToDevice, 0);

    dim3 blk(256);
    dim3 gp(DD / 128, MTOT / 64);     // (4, 64)  projections / ffn2
    dim3 g1(D2 / 128, MTOT / 64);     // (8, 64)  ffn1
    dim3 gfl(LL / 128, BB * HH);      // (16, 16) flash

    for (int l = 0; l < NLAYERS; l++) {
        const float* Wq = wq + (size_t)l * DD * DD;
        const float* Wk = wk + (size_t)l * DD * DD;
        const float* Wv = wv + (size_t)l * DD * DD;
        const float* Wo = wo + (size_t)l * DD * DD;
        const float* W1 = w1 + (size_t)l * DD * D2;
        const float* W2 = w2 + (size_t)l * D2 * DD;

        // ---- attention block ----
        ln_kernel<<<MTOT, blk>>>(x, ln_ag + l * DD, ln_ab + l * DD, ph);
        mma_gemm<0,0><<<gp, blk, GEMM_SMEM>>>(ph, DD, Wq, DD, bq + l * DD, nullptr, pq, DD, DD);
        mma_gemm<0,0><<<gp, blk, GEMM_SMEM>>>(ph, DD, Wk, DD, bk + l * DD, nullptr, pk, DD, DD);
        mma_gemm<0,0><<<gp, blk, GEMM_SMEM>>>(ph, DD, Wv, DD, bv + l * DD, nullptr, pv, DD, DD);
        flash_kernel<<<gfl, blk, FLASH_SMEM>>>(pq, pk, pv, mask, pctx);
        mma_gemm<0,1><<<gp, blk, GEMM_SMEM>>>(pctx, DD, Wo, DD, bo + l * DD, x, x, DD, DD);

        // ---- FFN block ----
        ln_kernel<<<MTOT, blk>>>(x, ln_fg + l * DD, ln_fb + l * DD, ph);
        mma_gemm<1,0><<<g1, blk, GEMM_SMEM>>>(ph, DD, W1, D2, b1 + l * D2, nullptr, pffn, D2, DD);
        mma_gemm<0,1><<<gp, blk, GEMM_SMEM>>>(pffn, D2, W2, DD, b2 + l * DD, x, x, DD, D2);
    }
}

// round 5
// speedup vs baseline: 3.9191x; 1.1607x over previous
#include <cuda_runtime.h>
#include <cuda_bf16.h>
#include <math.h>

#define BB 2
#define LL 2048
#define DD 512
#define HH 8
#define DHH 64
#define NLAYERS 3
#define D2 1024
#define MTOT (BB * LL)          // 4096 rows
#define D3 1536
#define EPS 1e-5f

// ---------------- scratch (device globals; no allocations allowed) ----------
__device__ float g_h   [MTOT * DD];
__device__ float g_qkv [(size_t)MTOT * D3];
__device__ float g_ctx [MTOT * DD];
__device__ float g_ffn [MTOT * D2];
// transposed weights (row-major [N][K]) + packed qkv bias
__device__ float g_qkvT[(size_t)NLAYERS * D3 * DD];
__device__ float g_oT  [(size_t)NLAYERS * DD * DD];
__device__ float g_w1T [(size_t)NLAYERS * D2 * DD];
__device__ float g_w2T [(size_t)NLAYERS * DD * D2];
__device__ float g_bqkv[NLAYERS * D3];

// mma.tf32 truncates fp32 operand mantissas in HW -> feed raw fp32 bits.
__device__ __forceinline__ void mma_tf32(float* c, const unsigned* a,
                                         unsigned b0, unsigned b1) {
    asm volatile(
        "mma.sync.aligned.m16n8k8.row.col.f32.tf32.tf32.f32 "
        "{%0,%1,%2,%3}, {%4,%5,%6,%7}, {%8,%9}, {%0,%1,%2,%3};"
        : "+f"(c[0]), "+f"(c[1]), "+f"(c[2]), "+f"(c[3])
        : "r"(a[0]), "r"(a[1]), "r"(a[2]), "r"(a[3]), "r"(b0), "r"(b1));
}

__device__ __forceinline__ void ldsm4(unsigned* r, unsigned addr) {
    asm volatile("ldmatrix.sync.aligned.m8n8.x4.shared.b16 {%0,%1,%2,%3}, [%4];"
                 : "=r"(r[0]), "=r"(r[1]), "=r"(r[2]), "=r"(r[3]) : "r"(addr));
}

__device__ __forceinline__ unsigned sptr(const void* p) {
    return (unsigned)__cvta_generic_to_shared(p);
}

__device__ __forceinline__ void cpa16(unsigned dst, const void* src) {
    asm volatile("cp.async.cg.shared.global [%0], [%1], 16;" :: "r"(dst), "l"(src));
}

// ---------------- weight transpose: dst[cols][rows] = src[rows][cols] ------
__global__ __launch_bounds__(256)
void transpose_kernel(const float* __restrict__ src, float* __restrict__ dst,
                      int rows, int cols) {
    __shared__ float t[32][33];
    int x = blockIdx.x * 32 + threadIdx.x;
    int y = blockIdx.y * 32 + threadIdx.y;
    #pragma unroll
    for (int j = 0; j < 32; j += 8)
        t[threadIdx.y + j][threadIdx.x] = src[(size_t)(y + j) * cols + x];
    __syncthreads();
    int x2 = blockIdx.y * 32 + threadIdx.x;
    int y2 = blockIdx.x * 32 + threadIdx.y;
    #pragma unroll
    for (int j = 0; j < 32; j += 8)
        dst[(size_t)(y2 + j) * rows + x2] = t[threadIdx.x][threadIdx.y + j];
}

// ---------------- LayerNorm: one block per row (D=512), 256 threads --------
__global__ __launch_bounds__(256)
void ln_kernel(const float* __restrict__ x, const float* __restrict__ g,
               const float* __restrict__ b, float* __restrict__ out) {
    int row = blockIdx.x;
    const float* xr = x + (size_t)row * DD;
    float*       orow = out + (size_t)row * DD;
    int t = threadIdx.x;
    float v0 = xr[t], v1 = xr[t + 256];
    float s  = v0 + v1;
    float sq = v0 * v0 + v1 * v1;

    __shared__ float red[8], red2[8];
    for (int o = 16; o > 0; o >>= 1) {
        s  += __shfl_down_sync(0xffffffffu, s,  o);
        sq += __shfl_down_sync(0xffffffffu, sq, o);
    }
    int warp = t >> 5, lane = t & 31;
    if (lane == 0) { red[warp] = s; red2[warp] = sq; }
    __syncthreads();
    __shared__ float s_mean, s_inv;
    if (t == 0) {
        float ts = 0.f, tq = 0.f;
        #pragma unroll
        for (int i = 0; i < 8; i++) { ts += red[i]; tq += red2[i]; }
        float mean = ts * (1.0f / DD);
        float var  = tq * (1.0f / DD) - mean * mean;
        s_mean = mean;
        s_inv  = rsqrtf(var + EPS);
    }
    __syncthreads();
    float mean = s_mean, inv = s_inv;
    orow[t]       = (v0 - mean) * inv * g[t]       + b[t];
    orow[t + 256] = (v1 - mean) * inv * g[t + 256] + b[t + 256];
}

// ---------------- tf32 ldmatrix tensor-core GEMM ---------------------------
// C = A @ Bt^T + bias [+res] [relu].  A row-major MxK, Bt row-major NxK.
// CTA 128x128x32, 256 threads (2x4 warps of 64x32), 3-stage cp.async pipeline.
// smem layout per operand: [row][8 chunks of 16B], chunk swizzled (c^row)&7.
#define GEMM_SMEM (3 * (128 + 128) * 32 * 4)
template<int RELU, int RES>
__global__ __launch_bounds__(256)
void mma_gemm(const float* __restrict__ A, int lda,
              const float* __restrict__ Bt, int ldb,
              const float* __restrict__ bias,
              const float* __restrict__ res,
              float* __restrict__ C, int ldc, int K)
{
    constexpr int BM = 128, BN = 128, BK = 32;
    constexpr int AW = BM * BK;   // words per A buffer
    constexpr int BW = BN * BK;
    extern __shared__ unsigned gsm[];
    unsigned* As = gsm;           // [3][128*32]
    unsigned* Bs = gsm + 3 * AW;  // [3][128*32]

    const int tid  = threadIdx.x;
    const int lane = tid & 31, warp = tid >> 5;
    const int g    = lane >> 2, tg = lane & 3;
    const int sub  = lane >> 3, rr = lane & 7;
    const int mW   = (warp >> 2) * 64, nW = (warp & 3) * 32;

    const int rowBase = blockIdx.y * BM;
    const int colBase = blockIdx.x * BN;
    const float* Ab  = A  + (size_t)rowBase * lda;
    const float* Btb = Bt + (size_t)colBase * ldb;
    float* Cb = C + (size_t)rowBase * ldc + colBase;

    // ldmatrix lane geometry
    const int aRow0 = (sub & 1) * 8 + rr;       // + mW + mt*16
    const int aClS  = sub >> 1;
    const int bRow0 = (sub >> 1) * 8 + rr;      // + nW + p*16
    const int bClS  = sub & 1;

    const unsigned aBase = sptr(As);
    const unsigned bBase = sptr(Bs);

    float acc[4][4][4];
    #pragma unroll
    for (int i = 0; i < 4; i++)
        #pragma unroll
        for (int j = 0; j < 4; j++)
            #pragma unroll
            for (int r = 0; r < 4; r++) acc[i][j][r] = 0.f;

    auto stage = [&](int kt, int buf) {
        const int k0 = kt * BK;
        unsigned* ad = As + buf * AW;
        unsigned* bd = Bs + buf * BW;
        #pragma unroll
        for (int i = 0; i < 4; i++) {
            int idx = i * 256 + tid;
            int row = idx >> 3, c = idx & 7;
            cpa16(sptr(ad + (row * 8 + ((c ^ row) & 7)) * 4),
                  Ab + (size_t)row * lda + k0 + c * 4);
        }
        #pragma unroll
        for (int i = 0; i < 4; i++) {
            int idx = i * 256 + tid;
            int n = idx >> 3, c = idx & 7;
            cpa16(sptr(bd + (n * 8 + ((c ^ n) & 7)) * 4),
                  Btb + (size_t)n * ldb + k0 + c * 4);
        }
        asm volatile("cp.async.commit_group;");
    };

    const int KT = K / BK;
    stage(0, 0);
    if (KT > 1) stage(1, 1);

    for (int kt = 0; kt < KT; kt++) {
        const int buf = kt % 3;
        if (kt + 1 < KT) asm volatile("cp.async.wait_group 1;");
        else             asm volatile("cp.async.wait_group 0;");
        __syncthreads();

        const unsigned aB = aBase + buf * AW * 4;
        const unsigned bB = bBase + buf * BW * 4;
        #pragma unroll
        for (int ksi = 0; ksi < 4; ksi++) {
            const int clb = ksi * 2;
            unsigned af[4][4], bf[2][4];
            #pragma unroll
            for (int mt = 0; mt < 4; mt++) {
                int row = mW + mt * 16 + aRow0;
                int cl  = clb + aClS;
                ldsm4(af[mt], aB + ((row * 8 + ((cl ^ row) & 7)) << 4));
            }
            #pragma unroll
            for (int p = 0; p < 2; p++) {
                int row = nW + p * 16 + bRow0;
                int cl  = clb + bClS;
                ldsm4(bf[p], bB + ((row * 8 + ((cl ^ row) & 7)) << 4));
            }
            #pragma unroll
            for (int mt = 0; mt < 4; mt++)
                #pragma unroll
                for (int nt = 0; nt < 4; nt++)
                    mma_tf32(acc[mt][nt], af[mt],
                             bf[nt >> 1][(nt & 1) * 2], bf[nt >> 1][(nt & 1) * 2 + 1]);
        }

        if (kt + 2 < KT) stage(kt + 2, (kt + 2) % 3);
        __syncthreads();
    }

    // epilogue
    #pragma unroll
    for (int mt = 0; mt < 4; mt++) {
        int r0 = mW + mt * 16 + g;
        #pragma unroll
        for (int nt = 0; nt < 4; nt++) {
            int c = nW + nt * 8 + 2 * tg;
            float2 bi = *(const float2*)(bias + colBase + c);
            float2 o0, o1;
            o0.x = acc[mt][nt][0] + bi.x; o0.y = acc[mt][nt][1] + bi.y;
            o1.x = acc[mt][nt][2] + bi.x; o1.y = acc[mt][nt][3] + bi.y;
            if (RES) {
                const float* rb = res + (size_t)rowBase * ldc + colBase;
                float2 q0 = *(const float2*)(rb + (size_t)r0 * ldc + c);
                float2 q1 = *(const float2*)(rb + (size_t)(r0 + 8) * ldc + c);
                o0.x += q0.x; o0.y += q0.y; o1.x += q1.x; o1.y += q1.y;
            }
            if (RELU) {
                o0.x = fmaxf(o0.x, 0.f); o0.y = fmaxf(o0.y, 0.f);
                o1.x = fmaxf(o1.x, 0.f); o1.y = fmaxf(o1.y, 0.f);
            }
            *(float2*)(Cb + (size_t)r0 * ldc + c) = o0;
            *(float2*)(Cb + (size_t)(r0 + 8) * ldc + c) = o1;
        }
    }
}

// ---------------- Flash attention ------------------------------------------
// grid = (L/128 q-tiles, B*H). 256 threads, warp owns 16 q-rows.
// Reads packed QKV [4096][1536]: q at +0, k at +512, v at +1024.
#define FQ_WORDS (128 * 64)
#define FK_WORDS (64 * 64)
#define FV_WORDS (64 * 72)
#define FLASH_SMEM ((FQ_WORDS + 2 * FK_WORDS + 2 * FV_WORDS + LL) * 4)

__global__ __launch_bounds__(256)
void flash_kernel(const float* __restrict__ qkv,
                  const unsigned char* __restrict__ mask,
                  float* __restrict__ ctx)
{
    extern __shared__ unsigned fsm[];
    unsigned* Qs = fsm;                         // [128][16 chunks] swizzled
    unsigned* Ks = Qs + FQ_WORDS;               // [2][64][16 chunks] swizzled
    unsigned* Vs = Ks + 2 * FK_WORDS;           // [2][64][72] plain
    float*    Ms = (float*)(Vs + 2 * FV_WORDS); // [2048] 0 / -inf

    const int tid  = threadIdx.x;
    const int lane = tid & 31, warp = tid >> 5;
    const int g    = lane >> 2, tg = lane & 3;
    const int sub  = lane >> 3, rr = lane & 7;
    const int bh   = blockIdx.y;
    const int b    = bh >> 3, h = bh & 7;
    const int q0   = blockIdx.x * 128;
    const int mW   = warp * 16;

    const float* qb = qkv + ((size_t)b * LL + q0) * D3 + h * DHH;
    const float* kb = qkv + (size_t)b * LL * D3 + 512  + h * DHH;
    const float* vb = qkv + (size_t)b * LL * D3 + 1024 + h * DHH;

    auto loadKV = [&](int tile, int buf) {
        int key0 = tile * 64;
        unsigned* kd = Ks + buf * FK_WORDS;
        unsigned* vd = Vs + buf * FV_WORDS;
        #pragma unroll
        for (int i = 0; i < 4; i++) {
            int idx = tid + i * 256;
            int row = idx >> 4, c = idx & 15;
            const float* sk = kb + (size_t)(key0 + row) * D3 + c * 4;
            const float* sv = vb + (size_t)(key0 + row) * D3 + c * 4;
            cpa16(sptr(kd + (row * 16 + ((c & 8) | ((c ^ row) & 7))) * 4), sk);
            cpa16(sptr(vd + row * 72 + c * 4), sv);
        }
        asm volatile("cp.async.commit_group;");
    };

    loadKV(0, 0);
    loadKV(1, 1);

    // Q tile -> swizzled smem (raw bits), mask -> smem
    #pragma unroll
    for (int i = 0; i < 8; i++) {
        int idx = tid + i * 256;
        int row = idx >> 4, c = idx & 15;
        float4 x = *(const float4*)(qb + (size_t)row * D3 + c * 4);
        uint4 u;
        u.x = __float_as_uint(x.x); u.y = __float_as_uint(x.y);
        u.z = __float_as_uint(x.z); u.w = __float_as_uint(x.w);
        *(uint4*)(Qs + (row * 16 + ((c & 8) | ((c ^ row) & 7))) * 4) = u;
    }
    const unsigned char* mrow = mask + (size_t)b * LL;
    #pragma unroll
    for (int i = 0; i < 8; i++) {
        int idx = tid + i * 256;
        Ms[idx] = mrow[idx] ? -INFINITY : 0.f;
    }
    __syncthreads();

    // Q fragments live in registers for the whole kernel (ldmatrix)
    const unsigned qBase = sptr(Qs);
    unsigned qf[8][4];
    #pragma unroll
    for (int kg = 0; kg < 8; kg++) {
        int row = mW + (sub & 1) * 8 + rr;
        int cl  = 2 * kg + (sub >> 1);
        ldsm4(qf[kg], qBase + ((row * 16 + ((cl & 8) | ((cl ^ row) & 7))) << 4));
    }

    float m0 = -1e30f, m1 = -1e30f, l0 = 0.f, l1 = 0.f;
    float o[8][4];
    #pragma unroll
    for (int nt = 0; nt < 8; nt++)
        #pragma unroll
        for (int j = 0; j < 4; j++) o[nt][j] = 0.f;

    const int srcA = (lane & ~3) | (tg >> 1);
    const int srcB = srcA + 2;
    const unsigned kBase = sptr(Ks);

    for (int t = 0; t < LL / 64; t++) {
        const int buf = t & 1;
        if (t == LL / 64 - 1) asm volatile("cp.async.wait_group 0;");
        else                  asm volatile("cp.async.wait_group 1;");
        __syncthreads();

        const unsigned kB = kBase + buf * FK_WORDS * 4;
        const unsigned* Vb = Vs + buf * FV_WORDS;

        // S = Q @ K^T  (warp: 16 x 64) via ldmatrix K fragments
        float s[8][4];
        #pragma unroll
        for (int nt = 0; nt < 8; nt++)
            #pragma unroll
            for (int j = 0; j < 4; j++) s[nt][j] = 0.f;
        #pragma unroll
        for (int kg = 0; kg < 8; kg++) {
            unsigned kf[4][4];
            #pragma unroll
            for (int p = 0; p < 4; p++) {
                int row = 16 * p + (sub >> 1) * 8 + rr;
                int cl  = 2 * kg + (sub & 1);
                ldsm4(kf[p], kB + ((row * 16 + ((cl & 8) | ((cl ^ row) & 7))) << 4));
            }
            #pragma unroll
            for (int nt = 0; nt < 8; nt++)
                mma_tf32(s[nt], qf[kg],
                         kf[nt >> 1][(nt & 1) * 2], kf[nt >> 1][(nt & 1) * 2 + 1]);
        }

        // scale + mask + online softmax
        const int key0 = t * 64;
        float rm0 = -INFINITY, rm1 = -INFINITY;
        #pragma unroll
        for (int nt = 0; nt < 8; nt++) {
            float ma = Ms[key0 + 8 * nt + 2 * tg];
            float mb = Ms[key0 + 8 * nt + 2 * tg + 1];
            s[nt][0] = s[nt][0] * 0.125f + ma;
            s[nt][1] = s[nt][1] * 0.125f + mb;
            s[nt][2] = s[nt][2] * 0.125f + ma;
            s[nt][3] = s[nt][3] * 0.125f + mb;
            rm0 = fmaxf(rm0, fmaxf(s[nt][0], s[nt][1]));
            rm1 = fmaxf(rm1, fmaxf(s[nt][2], s[nt][3]));
        }
        rm0 = fmaxf(rm0, __shfl_xor_sync(0xffffffffu, rm0, 1));
        rm0 = fmaxf(rm0, __shfl_xor_sync(0xffffffffu, rm0, 2));
        rm1 = fmaxf(rm1, __shfl_xor_sync(0xffffffffu, rm1, 1));
        rm1 = fmaxf(rm1, __shfl_xor_sync(0xffffffffu, rm1, 2));

        float mn0 = fmaxf(m0, rm0), mn1 = fmaxf(m1, rm1);
        float al0 = __expf(m0 - mn0), al1 = __expf(m1 - mn1);
        float sum0 = 0.f, sum1 = 0.f;
        #pragma unroll
        for (int nt = 0; nt < 8; nt++) {
            s[nt][0] = __expf(s[nt][0] - mn0);
            s[nt][1] = __expf(s[nt][1] - mn0);
            s[nt][2] = __expf(s[nt][2] - mn1);
            s[nt][3] = __expf(s[nt][3] - mn1);
            sum0 += s[nt][0] + s[nt][1];
            sum1 += s[nt][2] + s[nt][3];
        }
        sum0 += __shfl_xor_sync(0xffffffffu, sum0, 1);
        sum0 += __shfl_xor_sync(0xffffffffu, sum0, 2);
        sum1 += __shfl_xor_sync(0xffffffffu, sum1, 1);
        sum1 += __shfl_xor_sync(0xffffffffu, sum1, 2);
        l0 = l0 * al0 + sum0; l1 = l1 * al1 + sum1;
        m0 = mn0; m1 = mn1;
        #pragma unroll
        for (int nt = 0; nt < 8; nt++) {
            o[nt][0] *= al0; o[nt][1] *= al0;
            o[nt][2] *= al1; o[nt][3] *= al1;
        }

        // O += P @ V : shuffle P (accumulator layout) into A-fragment layout
        #pragma unroll
        for (int kg = 0; kg < 8; kg++) {
            float w0, w1;
            unsigned a[4];
            w0 = __shfl_sync(0xffffffffu, s[kg][0], srcA);
            w1 = __shfl_sync(0xffffffffu, s[kg][1], srcA);
            a[0] = __float_as_uint((tg & 1) ? w1 : w0);
            w0 = __shfl_sync(0xffffffffu, s[kg][2], srcA);
            w1 = __shfl_sync(0xffffffffu, s[kg][3], srcA);
            a[1] = __float_as_uint((tg & 1) ? w1 : w0);
            w0 = __shfl_sync(0xffffffffu, s[kg][0], srcB);
            w1 = __shfl_sync(0xffffffffu, s[kg][1], srcB);
            a[2] = __float_as_uint((tg & 1) ? w1 : w0);
            w0 = __shfl_sync(0xffffffffu, s[kg][2], srcB);
            w1 = __shfl_sync(0xffffffffu, s[kg][3], srcB);
            a[3] = __float_as_uint((tg & 1) ? w1 : w0);
            #pragma unroll
            for (int nt = 0; nt < 8; nt++) {
                unsigned b0 = Vb[(8 * kg + tg)     * 72 + 8 * nt + g];
                unsigned b1 = Vb[(8 * kg + tg + 4) * 72 + 8 * nt + g];
                mma_tf32(o[nt], a, b0, b1);
            }
        }
        __syncthreads();
        if (t + 2 < LL / 64) loadKV(t + 2, buf);
    }

    // normalize + write ctx
    float i0 = 1.f / l0, i1 = 1.f / l1;
    float* cb = ctx + ((size_t)b * LL + q0 + mW) * DD + h * DHH;
    #pragma unroll
    for (int nt = 0; nt < 8; nt++) {
        int c = 8 * nt + 2 * tg;
        float2 u0, u1;
        u0.x = o[nt][0] * i0; u0.y = o[nt][1] * i0;
        u1.x = o[nt][2] * i1; u1.y = o[nt][3] * i1;
        *(float2*)(cb + (size_t)g * DD + c) = u0;
        *(float2*)(cb + (size_t)(g + 8) * DD + c) = u1;
    }
}

// ---------------------------------------------------------------------------
extern "C" void kernel_launch(void* const* d_in, const int* in_sizes, int n_in,
                              void* d_out, int out_size) {
    (void)in_sizes; (void)n_in; (void)out_size;
    const float* x_in  = (const float*)d_in[0];
    const unsigned char* mask = (const unsigned char*)d_in[1];
    const float* ln_ag = (const float*)d_in[2];
    const float* ln_ab = (const float*)d_in[3];
    const float* wq = (const float*)d_in[4];
    const float* bq = (const float*)d_in[5];
    const float* wk = (const float*)d_in[6];
    const float* bk = (const float*)d_in[7];
    const float* wv = (const float*)d_in[8];
    const float* bv = (const float*)d_in[9];
    const float* wo = (const float*)d_in[10];
    const float* bo = (const float*)d_in[11];
    const float* ln_fg = (const float*)d_in[12];
    const float* ln_fb = (const float*)d_in[13];
    const float* w1 = (const float*)d_in[14];
    const float* b1 = (const float*)d_in[15];
    const float* w2 = (const float*)d_in[16];
    const float* b2 = (const float*)d_in[17];

    float* x = (float*)d_out;   // residual stream lives in the output buffer

    float *ph, *pqkv, *pctx, *pffn, *pqkvT, *poT, *pw1T, *pw2T, *pbqkv;
    cudaGetSymbolAddress((void**)&ph,    g_h);
    cudaGetSymbolAddress((void**)&pqkv,  g_qkv);
    cudaGetSymbolAddress((void**)&pctx,  g_ctx);
    cudaGetSymbolAddress((void**)&pffn,  g_ffn);
    cudaGetSymbolAddress((void**)&pqkvT, g_qkvT);
    cudaGetSymbolAddress((void**)&poT,   g_oT);
    cudaGetSymbolAddress((void**)&pw1T,  g_w1T);
    cudaGetSymbolAddress((void**)&pw2T,  g_w2T);
    cudaGetSymbolAddress((void**)&pbqkv, g_bqkv);

    cudaFuncSetAttribute(flash_kernel,
                         cudaFuncAttributeMaxDynamicSharedMemorySize, FLASH_SMEM);
    cudaFuncSetAttribute(mma_gemm<0,0>,
                         cudaFuncAttributeMaxDynamicSharedMemorySize, GEMM_SMEM);
    cudaFuncSetAttribute(mma_gemm<0,1>,
                         cudaFuncAttributeMaxDynamicSharedMemorySize, GEMM_SMEM);
    cudaFuncSetAttribute(mma_gemm<1,0>,
                         cudaFuncAttributeMaxDynamicSharedMemorySize, GEMM_SMEM);

    cudaMemcpyAsync(x, x_in, (size_t)MTOT * DD * sizeof(float),
                    cudaMemcpyDeviceToDevice, 0);

    // ---- weight transposes + bias packing (once per launch) ----
    dim3 tb(32, 8);
    dim3 t512(DD / 32, DD / 32);
    dim3 t1(D2 / 32, DD / 32);   // w1 [512][1024]
    dim3 t2(DD / 32, D2 / 32);   // w2 [1024][512]
    for (int l = 0; l < NLAYERS; l++) {
        transpose_kernel<<<t512, tb>>>(wq + (size_t)l * DD * DD,
                                       pqkvT + (size_t)l * D3 * DD, DD, DD);
        transpose_kernel<<<t512, tb>>>(wk + (size_t)l * DD * DD,
                                       pqkvT + (size_t)l * D3 * DD + (size_t)DD * DD, DD, DD);
        transpose_kernel<<<t512, tb>>>(wv + (size_t)l * DD * DD,
                                       pqkvT + (size_t)l * D3 * DD + (size_t)2 * DD * DD, DD, DD);
        transpose_kernel<<<t512, tb>>>(wo + (size_t)l * DD * DD,
                                       poT + (size_t)l * DD * DD, DD, DD);
        transpose_kernel<<<t1, tb>>>(w1 + (size_t)l * DD * D2,
                                     pw1T + (size_t)l * D2 * DD, DD, D2);
        transpose_kernel<<<t2, tb>>>(w2 + (size_t)l * D2 * DD,
                                     pw2T + (size_t)l * DD * D2, D2, DD);
        cudaMemcpyAsync(pbqkv + l * D3,        bq + l * DD, DD * 4,
                        cudaMemcpyDeviceToDevice, 0);
        cudaMemcpyAsync(pbqkv + l * D3 + 512,  bk + l * DD, DD * 4,
                        cudaMemcpyDeviceToDevice, 0);
        cudaMemcpyAsync(pbqkv + l * D3 + 1024, bv + l * DD, DD * 4,
                        cudaMemcpyDeviceToDevice, 0);
    }

    dim3 blk(256);
    dim3 gqkv(D3 / 128, MTOT / 128);  // (12, 32)
    dim3 gp(DD / 128, MTOT / 128);    // (4, 32)
    dim3 g1(D2 / 128, MTOT / 128);    // (8, 32)
    dim3 gfl(LL / 128, BB * HH);      // (16, 16)

    for (int l = 0; l < NLAYERS; l++) {
        // ---- attention block ----
        ln_kernel<<<MTOT, blk>>>(x, ln_ag + l * DD, ln_ab + l * DD, ph);
        mma_gemm<0,0><<<gqkv, blk, GEMM_SMEM>>>(
            ph, DD, pqkvT + (size_t)l * D3 * DD, DD, pbqkv + l * D3,
            nullptr, pqkv, D3, DD);
        flash_kernel<<<gfl, blk, FLASH_SMEM>>>(pqkv, mask, pctx);
        mma_gemm<0,1><<<gp, blk, GEMM_SMEM>>>(
            pctx, DD, poT + (size_t)l * DD * DD, DD, bo + l * DD, x, x, DD, DD);

        // ---- FFN block ----
        ln_kernel<<<MTOT, blk>>>(x, ln_fg + l * DD, ln_fb + l * DD, ph);
        mma_gemm<1,0><<<g1, blk, GEMM_SMEM>>>(
            ph, DD, pw1T + (size_t)l * D2 * DD, DD, b1 + l * D2,
            nullptr, pffn, D2, DD);
        mma_gemm<0,1><<<gp, blk, GEMM_SMEM>>>(
            pffn, D2, pw2T + (size_t)l * DD * D2, D2, b2 + l * DD, x, x, DD, D2);
    }
}

// round 6
// speedup vs baseline: 4.1235x; 1.0522x over previous
#include <cuda_runtime.h>
#include <cuda_bf16.h>
#include <math.h>

#define BB 2
#define LL 2048
#define DD 512
#define HH 8
#define DHH 64
#define NLAYERS 3
#define D2 1024
#define MTOT (BB * LL)          // 4096 rows
#define D3 1536
#define EPS 1e-5f

// ---------------- scratch (device globals; no allocations allowed) ----------
__device__ float g_h   [MTOT * DD];
__device__ float g_qkv [(size_t)MTOT * D3];
__device__ float g_ctx [MTOT * DD];
__device__ float g_ffn [MTOT * D2];
// transposed weights (row-major [N][K]) + packed qkv bias
__device__ float g_qkvT[(size_t)NLAYERS * D3 * DD];
__device__ float g_oT  [(size_t)NLAYERS * DD * DD];
__device__ float g_w1T [(size_t)NLAYERS * D2 * DD];
__device__ float g_w2T [(size_t)NLAYERS * DD * D2];
__device__ float g_bqkv[NLAYERS * D3];

// mma.tf32 truncates fp32 operand mantissas in HW -> feed raw fp32 bits.
__device__ __forceinline__ void mma_tf32(float* c, const unsigned* a,
                                         unsigned b0, unsigned b1) {
    asm volatile(
        "mma.sync.aligned.m16n8k8.row.col.f32.tf32.tf32.f32 "
        "{%0,%1,%2,%3}, {%4,%5,%6,%7}, {%8,%9}, {%0,%1,%2,%3};"
        : "+f"(c[0]), "+f"(c[1]), "+f"(c[2]), "+f"(c[3])
        : "r"(a[0]), "r"(a[1]), "r"(a[2]), "r"(a[3]), "r"(b0), "r"(b1));
}

__device__ __forceinline__ void ldsm4(unsigned* r, unsigned addr) {
    asm volatile("ldmatrix.sync.aligned.m8n8.x4.shared.b16 {%0,%1,%2,%3}, [%4];"
                 : "=r"(r[0]), "=r"(r[1]), "=r"(r[2]), "=r"(r[3]) : "r"(addr));
}

__device__ __forceinline__ unsigned sptr(const void* p) {
    return (unsigned)__cvta_generic_to_shared(p);
}

__device__ __forceinline__ void cpa16(unsigned dst, const void* src) {
    asm volatile("cp.async.cg.shared.global [%0], [%1], 16;" :: "r"(dst), "l"(src));
}

// ---------------- fused prep: ALL weight transposes + bias packing ---------
// 6144 tile blocks (2048/layer) + 18 bias blocks. One launch per replay.
#define PREP_BLOCKS (6144 + 18)
__global__ __launch_bounds__(256)
void prep_kernel(const float* __restrict__ wq, const float* __restrict__ wk,
                 const float* __restrict__ wv, const float* __restrict__ wo,
                 const float* __restrict__ w1, const float* __restrict__ w2,
                 const float* __restrict__ bq, const float* __restrict__ bk,
                 const float* __restrict__ bv,
                 float* __restrict__ qkvT, float* __restrict__ oT,
                 float* __restrict__ w1T, float* __restrict__ w2T,
                 float* __restrict__ bqkv)
{
    int bid = blockIdx.x;
    if (bid >= 6144) {                       // bias packing tail
        int gi = (bid - 6144) * 256 + threadIdx.x;
        if (gi < NLAYERS * D3) {
            int l = gi / D3, p = gi % D3;
            float v = (p < 512) ? bq[l * DD + p]
                    : (p < 1024) ? bk[l * DD + p - 512]
                                 : bv[l * DD + p - 1024];
            bqkv[gi] = v;
        }
        return;
    }
    int l = bid / 2048, seg = bid % 2048;
    const float* src; float* dst; int R, C, gx, gy;
    if (seg < 1024) {                        // 512x512 transposes
        int which = seg >> 8, t = seg & 255;
        R = DD; C = DD; gx = t & 15; gy = t >> 4;
        if (which == 0)      { src = wq + (size_t)l*DD*DD; dst = qkvT + (size_t)l*D3*DD; }
        else if (which == 1) { src = wk + (size_t)l*DD*DD; dst = qkvT + (size_t)l*D3*DD + (size_t)DD*DD; }
        else if (which == 2) { src = wv + (size_t)l*DD*DD; dst = qkvT + (size_t)l*D3*DD + (size_t)2*DD*DD; }
        else                 { src = wo + (size_t)l*DD*DD; dst = oT   + (size_t)l*DD*DD; }
    } else if (seg < 1536) {                 // w1 [512][1024]
        int t = seg - 1024;
        R = DD; C = D2; gx = t & 31; gy = t >> 5;
        src = w1 + (size_t)l*DD*D2; dst = w1T + (size_t)l*D2*DD;
    } else {                                 // w2 [1024][512]
        int t = seg - 1536;
        R = D2; C = DD; gx = t & 15; gy = t >> 4;
        src = w2 + (size_t)l*D2*DD; dst = w2T + (size_t)l*DD*D2;
    }
    __shared__ float s[32][33];
    int tx = threadIdx.x & 31, ty = threadIdx.x >> 5;
    int x = gx * 32 + tx, y = gy * 32 + ty;
    #pragma unroll
    for (int j = 0; j < 32; j += 8)
        s[ty + j][tx] = src[(size_t)(y + j) * C + x];
    __syncthreads();
    int x2 = gy * 32 + tx, y2 = gx * 32 + ty;
    #pragma unroll
    for (int j = 0; j < 32; j += 8)
        dst[(size_t)(y2 + j) * R + x2] = s[tx][ty + j];
}

// ---------------- LayerNorm: one block per row (D=512), 256 threads --------
__global__ __launch_bounds__(256)
void ln_kernel(const float* __restrict__ x, const float* __restrict__ g,
               const float* __restrict__ b, float* __restrict__ out) {
    int row = blockIdx.x;
    const float* xr = x + (size_t)row * DD;
    float*       orow = out + (size_t)row * DD;
    int t = threadIdx.x;
    float v0 = xr[t], v1 = xr[t + 256];
    float s  = v0 + v1;
    float sq = v0 * v0 + v1 * v1;

    __shared__ float red[8], red2[8];
    for (int o = 16; o > 0; o >>= 1) {
        s  += __shfl_down_sync(0xffffffffu, s,  o);
        sq += __shfl_down_sync(0xffffffffu, sq, o);
    }
    int warp = t >> 5, lane = t & 31;
    if (lane == 0) { red[warp] = s; red2[warp] = sq; }
    __syncthreads();
    __shared__ float s_mean, s_inv;
    if (t == 0) {
        float ts = 0.f, tq = 0.f;
        #pragma unroll
        for (int i = 0; i < 8; i++) { ts += red[i]; tq += red2[i]; }
        float mean = ts * (1.0f / DD);
        float var  = tq * (1.0f / DD) - mean * mean;
        s_mean = mean;
        s_inv  = rsqrtf(var + EPS);
    }
    __syncthreads();
    float mean = s_mean, inv = s_inv;
    orow[t]       = (v0 - mean) * inv * g[t]       + b[t];
    orow[t + 256] = (v1 - mean) * inv * g[t + 256] + b[t + 256];
}

// ---------------- tf32 ldmatrix tensor-core GEMM ---------------------------
// C = A @ Bt^T + bias [+res] [relu].  A row-major MxK, Bt row-major NxK.
// CTA 128x128x32, 256 threads (2x4 warps of 64x32), 3-stage cp.async pipeline.
// smem layout per operand: [row][8 chunks of 16B], chunk swizzled (c^row)&7.
#define GEMM_SMEM (3 * (128 + 128) * 32 * 4)
template<int RELU, int RES>
__global__ __launch_bounds__(256)
void mma_gemm(const float* __restrict__ A, int lda,
              const float* __restrict__ Bt, int ldb,
              const float* __restrict__ bias,
              const float* __restrict__ res,
              float* __restrict__ C, int ldc, int K)
{
    constexpr int BM = 128, BN = 128, BK = 32;
    constexpr int AW = BM * BK;   // words per A buffer
    constexpr int BW = BN * BK;
    extern __shared__ unsigned gsm[];
    unsigned* As = gsm;           // [3][128*32]
    unsigned* Bs = gsm + 3 * AW;  // [3][128*32]

    const int tid  = threadIdx.x;
    const int lane = tid & 31, warp = tid >> 5;
    const int g    = lane >> 2, tg = lane & 3;
    const int sub  = lane >> 3, rr = lane & 7;
    const int mW   = (warp >> 2) * 64, nW = (warp & 3) * 32;

    const int rowBase = blockIdx.y * BM;
    const int colBase = blockIdx.x * BN;
    const float* Ab  = A  + (size_t)rowBase * lda;
    const float* Btb = Bt + (size_t)colBase * ldb;
    float* Cb = C + (size_t)rowBase * ldc + colBase;

    // ldmatrix lane geometry
    const int aRow0 = (sub & 1) * 8 + rr;       // + mW + mt*16
    const int aClS  = sub >> 1;
    const int bRow0 = (sub >> 1) * 8 + rr;      // + nW + p*16
    const int bClS  = sub & 1;

    const unsigned aBase = sptr(As);
    const unsigned bBase = sptr(Bs);

    float acc[4][4][4];
    #pragma unroll
    for (int i = 0; i < 4; i++)
        #pragma unroll
        for (int j = 0; j < 4; j++)
            #pragma unroll
            for (int r = 0; r < 4; r++) acc[i][j][r] = 0.f;

    auto stage = [&](int kt, int buf) {
        const int k0 = kt * BK;
        unsigned* ad = As + buf * AW;
        unsigned* bd = Bs + buf * BW;
        #pragma unroll
        for (int i = 0; i < 4; i++) {
            int idx = i * 256 + tid;
            int row = idx >> 3, c = idx & 7;
            cpa16(sptr(ad + (row * 8 + ((c ^ row) & 7)) * 4),
                  Ab + (size_t)row * lda + k0 + c * 4);
        }
        #pragma unroll
        for (int i = 0; i < 4; i++) {
            int idx = i * 256 + tid;
            int n = idx >> 3, c = idx & 7;
            cpa16(sptr(bd + (n * 8 + ((c ^ n) & 7)) * 4),
                  Btb + (size_t)n * ldb + k0 + c * 4);
        }
        asm volatile("cp.async.commit_group;");
    };

    const int KT = K / BK;
    stage(0, 0);
    if (KT > 1) stage(1, 1);

    for (int kt = 0; kt < KT; kt++) {
        const int buf = kt % 3;
        if (kt + 1 < KT) asm volatile("cp.async.wait_group 1;");
        else             asm volatile("cp.async.wait_group 0;");
        __syncthreads();

        const unsigned aB = aBase + buf * AW * 4;
        const unsigned bB = bBase + buf * BW * 4;
        #pragma unroll
        for (int ksi = 0; ksi < 4; ksi++) {
            const int clb = ksi * 2;
            unsigned af[4][4], bf[2][4];
            #pragma unroll
            for (int mt = 0; mt < 4; mt++) {
                int row = mW + mt * 16 + aRow0;
                int cl  = clb + aClS;
                ldsm4(af[mt], aB + ((row * 8 + ((cl ^ row) & 7)) << 4));
            }
            #pragma unroll
            for (int p = 0; p < 2; p++) {
                int row = nW + p * 16 + bRow0;
                int cl  = clb + bClS;
                ldsm4(bf[p], bB + ((row * 8 + ((cl ^ row) & 7)) << 4));
            }
            #pragma unroll
            for (int mt = 0; mt < 4; mt++)
                #pragma unroll
                for (int nt = 0; nt < 4; nt++)
                    mma_tf32(acc[mt][nt], af[mt],
                             bf[nt >> 1][(nt & 1) * 2], bf[nt >> 1][(nt & 1) * 2 + 1]);
        }

        if (kt + 2 < KT) stage(kt + 2, (kt + 2) % 3);
        __syncthreads();
    }

    // epilogue
    #pragma unroll
    for (int mt = 0; mt < 4; mt++) {
        int r0 = mW + mt * 16 + g;
        #pragma unroll
        for (int nt = 0; nt < 4; nt++) {
            int c = nW + nt * 8 + 2 * tg;
            float2 bi = *(const float2*)(bias + colBase + c);
            float2 o0, o1;
            o0.x = acc[mt][nt][0] + bi.x; o0.y = acc[mt][nt][1] + bi.y;
            o1.x = acc[mt][nt][2] + bi.x; o1.y = acc[mt][nt][3] + bi.y;
            if (RES) {
                const float* rb = res + (size_t)rowBase * ldc + colBase;
                float2 q0 = *(const float2*)(rb + (size_t)r0 * ldc + c);
                float2 q1 = *(const float2*)(rb + (size_t)(r0 + 8) * ldc + c);
                o0.x += q0.x; o0.y += q0.y; o1.x += q1.x; o1.y += q1.y;
            }
            if (RELU) {
                o0.x = fmaxf(o0.x, 0.f); o0.y = fmaxf(o0.y, 0.f);
                o1.x = fmaxf(o1.x, 0.f); o1.y = fmaxf(o1.y, 0.f);
            }
            *(float2*)(Cb + (size_t)r0 * ldc + c) = o0;
            *(float2*)(Cb + (size_t)(r0 + 8) * ldc + c) = o1;
        }
    }
}

// ---------------- Flash attention ------------------------------------------
// grid = (L/128 q-tiles, B*H). 256 threads, warp owns 16 q-rows.
// Reads packed QKV [4096][1536]: q at +0, k at +512, v at +1024.
// smem kept <= 113KB so 2 CTAs/SM fit.
#define FQ_WORDS (128 * 64)
#define FK_WORDS (64 * 64)
#define FV_WORDS (64 * 72)
#define FLASH_SMEM ((FQ_WORDS + 2 * FK_WORDS + 2 * FV_WORDS + LL) * 4)

__global__ __launch_bounds__(256)
void flash_kernel(const float* __restrict__ qkv,
                  const unsigned char* __restrict__ mask,
                  float* __restrict__ ctx)
{
    extern __shared__ unsigned fsm[];
    unsigned* Qs = fsm;                         // [128][16 chunks] swizzled
    unsigned* Ks = Qs + FQ_WORDS;               // [2][64][16 chunks] swizzled
    unsigned* Vs = Ks + 2 * FK_WORDS;           // [2][64][72] plain
    float*    Ms = (float*)(Vs + 2 * FV_WORDS); // [2048] 0 / -inf

    const int tid  = threadIdx.x;
    const int lane = tid & 31, warp = tid >> 5;
    const int g    = lane >> 2, tg = lane & 3;
    const int sub  = lane >> 3, rr = lane & 7;
    const int bh   = blockIdx.y;
    const int b    = bh >> 3, h = bh & 7;
    const int q0   = blockIdx.x * 128;
    const int mW   = warp * 16;

    const float* qb = qkv + ((size_t)b * LL + q0) * D3 + h * DHH;
    const float* kb = qkv + (size_t)b * LL * D3 + 512  + h * DHH;
    const float* vb = qkv + (size_t)b * LL * D3 + 1024 + h * DHH;

    auto loadKV = [&](int tile, int buf) {
        int key0 = tile * 64;
        unsigned* kd = Ks + buf * FK_WORDS;
        unsigned* vd = Vs + buf * FV_WORDS;
        #pragma unroll
        for (int i = 0; i < 4; i++) {
            int idx = tid + i * 256;
            int row = idx >> 4, c = idx & 15;
            const float* sk = kb + (size_t)(key0 + row) * D3 + c * 4;
            const float* sv = vb + (size_t)(key0 + row) * D3 + c * 4;
            cpa16(sptr(kd + (row * 16 + ((c & 8) | ((c ^ row) & 7))) * 4), sk);
            cpa16(sptr(vd + row * 72 + c * 4), sv);
        }
        asm volatile("cp.async.commit_group;");
    };

    loadKV(0, 0);
    loadKV(1, 1);

    // Q tile -> swizzled smem (raw bits), mask -> smem
    #pragma unroll
    for (int i = 0; i < 8; i++) {
        int idx = tid + i * 256;
        int row = idx >> 4, c = idx & 15;
        float4 x = *(const float4*)(qb + (size_t)row * D3 + c * 4);
        uint4 u;
        u.x = __float_as_uint(x.x); u.y = __float_as_uint(x.y);
        u.z = __float_as_uint(x.z); u.w = __float_as_uint(x.w);
        *(uint4*)(Qs + (row * 16 + ((c & 8) | ((c ^ row) & 7))) * 4) = u;
    }
    const unsigned char* mrow = mask + (size_t)b * LL;
    #pragma unroll
    for (int i = 0; i < 8; i++) {
        int idx = tid + i * 256;
        Ms[idx] = mrow[idx] ? -INFINITY : 0.f;
    }
    __syncthreads();

    // Q fragments live in registers for the whole kernel (ldmatrix)
    const unsigned qBase = sptr(Qs);
    unsigned qf[8][4];
    #pragma unroll
    for (int kg = 0; kg < 8; kg++) {
        int row = mW + (sub & 1) * 8 + rr;
        int cl  = 2 * kg + (sub >> 1);
        ldsm4(qf[kg], qBase + ((row * 16 + ((cl & 8) | ((cl ^ row) & 7))) << 4));
    }

    float m0 = -1e30f, m1 = -1e30f, l0 = 0.f, l1 = 0.f;
    float o[8][4];
    #pragma unroll
    for (int nt = 0; nt < 8; nt++)
        #pragma unroll
        for (int j = 0; j < 4; j++) o[nt][j] = 0.f;

    const int srcA = (lane & ~3) | (tg >> 1);
    const int srcB = srcA + 2;
    const unsigned kBase = sptr(Ks);

    for (int t = 0; t < LL / 64; t++) {
        const int buf = t & 1;
        if (t == LL / 64 - 1) asm volatile("cp.async.wait_group 0;");
        else                  asm volatile("cp.async.wait_group 1;");
        __syncthreads();

        const unsigned kB = kBase + buf * FK_WORDS * 4;
        const unsigned* Vb = Vs + buf * FV_WORDS;

        // S = Q @ K^T  (warp: 16 x 64) via ldmatrix K fragments
        float s[8][4];
        #pragma unroll
        for (int nt = 0; nt < 8; nt++)
            #pragma unroll
            for (int j = 0; j < 4; j++) s[nt][j] = 0.f;
        #pragma unroll
        for (int kg = 0; kg < 8; kg++) {
            unsigned kf[4][4];
            #pragma unroll
            for (int p = 0; p < 4; p++) {
                int row = 16 * p + (sub >> 1) * 8 + rr;
                int cl  = 2 * kg + (sub & 1);
                ldsm4(kf[p], kB + ((row * 16 + ((cl & 8) | ((cl ^ row) & 7))) << 4));
            }
            #pragma unroll
            for (int nt = 0; nt < 8; nt++)
                mma_tf32(s[nt], qf[kg],
                         kf[nt >> 1][(nt & 1) * 2], kf[nt >> 1][(nt & 1) * 2 + 1]);
        }

        // scale + mask + online softmax
        const int key0 = t * 64;
        float rm0 = -INFINITY, rm1 = -INFINITY;
        #pragma unroll
        for (int nt = 0; nt < 8; nt++) {
            float ma = Ms[key0 + 8 * nt + 2 * tg];
            float mb = Ms[key0 + 8 * nt + 2 * tg + 1];
            s[nt][0] = s[nt][0] * 0.125f + ma;
            s[nt][1] = s[nt][1] * 0.125f + mb;
            s[nt][2] = s[nt][2] * 0.125f + ma;
            s[nt][3] = s[nt][3] * 0.125f + mb;
            rm0 = fmaxf(rm0, fmaxf(s[nt][0], s[nt][1]));
            rm1 = fmaxf(rm1, fmaxf(s[nt][2], s[nt][3]));
        }
        rm0 = fmaxf(rm0, __shfl_xor_sync(0xffffffffu, rm0, 1));
        rm0 = fmaxf(rm0, __shfl_xor_sync(0xffffffffu, rm0, 2));
        rm1 = fmaxf(rm1, __shfl_xor_sync(0xffffffffu, rm1, 1));
        rm1 = fmaxf(rm1, __shfl_xor_sync(0xffffffffu, rm1, 2));

        float mn0 = fmaxf(m0, rm0), mn1 = fmaxf(m1, rm1);
        float al0 = __expf(m0 - mn0), al1 = __expf(m1 - mn1);
        float sum0 = 0.f, sum1 = 0.f;
        #pragma unroll
        for (int nt = 0; nt < 8; nt++) {
            s[nt][0] = __expf(s[nt][0] - mn0);
            s[nt][1] = __expf(s[nt][1] - mn0);
            s[nt][2] = __expf(s[nt][2] - mn1);
            s[nt][3] = __expf(s[nt][3] - mn1);
            sum0 += s[nt][0] + s[nt][1];
            sum1 += s[nt][2] + s[nt][3];
        }
        sum0 += __shfl_xor_sync(0xffffffffu, sum0, 1);
        sum0 += __shfl_xor_sync(0xffffffffu, sum0, 2);
        sum1 += __shfl_xor_sync(0xffffffffu, sum1, 1);
        sum1 += __shfl_xor_sync(0xffffffffu, sum1, 2);
        l0 = l0 * al0 + sum0; l1 = l1 * al1 + sum1;
        m0 = mn0; m1 = mn1;
        #pragma unroll
        for (int nt = 0; nt < 8; nt++) {
            o[nt][0] *= al0; o[nt][1] *= al0;
            o[nt][2] *= al1; o[nt][3] *= al1;
        }

        // O += P @ V : shuffle P (accumulator layout) into A-fragment layout
        #pragma unroll
        for (int kg = 0; kg < 8; kg++) {
            float w0, w1;
            unsigned a[4];
            w0 = __shfl_sync(0xffffffffu, s[kg][0], srcA);
            w1 = __shfl_sync(0xffffffffu, s[kg][1], srcA);
            a[0] = __float_as_uint((tg & 1) ? w1 : w0);
            w0 = __shfl_sync(0xffffffffu, s[kg][2], srcA);
            w1 = __shfl_sync(0xffffffffu, s[kg][3], srcA);
            a[1] = __float_as_uint((tg & 1) ? w1 : w0);
            w0 = __shfl_sync(0xffffffffu, s[kg][0], srcB);
            w1 = __shfl_sync(0xffffffffu, s[kg][1], srcB);
            a[2] = __float_as_uint((tg & 1) ? w1 : w0);
            w0 = __shfl_sync(0xffffffffu, s[kg][2], srcB);
            w1 = __shfl_sync(0xffffffffu, s[kg][3], srcB);
            a[3] = __float_as_uint((tg & 1) ? w1 : w0);
            #pragma unroll
            for (int nt = 0; nt < 8; nt++) {
                unsigned b0 = Vb[(8 * kg + tg)     * 72 + 8 * nt + g];
                unsigned b1 = Vb[(8 * kg + tg + 4) * 72 + 8 * nt + g];
                mma_tf32(o[nt], a, b0, b1);
            }
        }
        __syncthreads();
        if (t + 2 < LL / 64) loadKV(t + 2, buf);
    }

    // normalize + write ctx
    float i0 = 1.f / l0, i1 = 1.f / l1;
    float* cb = ctx + ((size_t)b * LL + q0 + mW) * DD + h * DHH;
    #pragma unroll
    for (int nt = 0; nt < 8; nt++) {
        int c = 8 * nt + 2 * tg;
        float2 u0, u1;
        u0.x = o[nt][0] * i0; u0.y = o[nt][1] * i0;
        u1.x = o[nt][2] * i1; u1.y = o[nt][3] * i1;
        *(float2*)(cb + (size_t)g * DD + c) = u0;
        *(float2*)(cb + (size_t)(g + 8) * DD + c) = u1;
    }
}

// ---------------------------------------------------------------------------
extern "C" void kernel_launch(void* const* d_in, const int* in_sizes, int n_in,
                              void* d_out, int out_size) {
    (void)in_sizes; (void)n_in; (void)out_size;
    const float* x_in  = (const float*)d_in[0];
    const unsigned char* mask = (const unsigned char*)d_in[1];
    const float* ln_ag = (const float*)d_in[2];
    const float* ln_ab = (const float*)d_in[3];
    const float* wq = (const float*)d_in[4];
    const float* bq = (const float*)d_in[5];
    const float* wk = (const float*)d_in[6];
    const float* bk = (const float*)d_in[7];
    const float* wv = (const float*)d_in[8];
    const float* bv = (const float*)d_in[9];
    const float* wo = (const float*)d_in[10];
    const float* bo = (const float*)d_in[11];
    const float* ln_fg = (const float*)d_in[12];
    const float* ln_fb = (const float*)d_in[13];
    const float* w1 = (const float*)d_in[14];
    const float* b1 = (const float*)d_in[15];
    const float* w2 = (const float*)d_in[16];
    const float* b2 = (const float*)d_in[17];

    float* x = (float*)d_out;   // residual stream lives in the output buffer

    float *ph, *pqkv, *pctx, *pffn, *pqkvT, *poT, *pw1T, *pw2T, *pbqkv;
    cudaGetSymbolAddress((void**)&ph,    g_h);
    cudaGetSymbolAddress((void**)&pqkv,  g_qkv);
    cudaGetSymbolAddress((void**)&pctx,  g_ctx);
    cudaGetSymbolAddress((void**)&pffn,  g_ffn);
    cudaGetSymbolAddress((void**)&pqkvT, g_qkvT);
    cudaGetSymbolAddress((void**)&poT,   g_oT);
    cudaGetSymbolAddress((void**)&pw1T,  g_w1T);
    cudaGetSymbolAddress((void**)&pw2T,  g_w2T);
    cudaGetSymbolAddress((void**)&pbqkv, g_bqkv);

    cudaFuncSetAttribute(flash_kernel,
                         cudaFuncAttributeMaxDynamicSharedMemorySize, FLASH_SMEM);
    cudaFuncSetAttribute(mma_gemm<0,0>,
                         cudaFuncAttributeMaxDynamicSharedMemorySize, GEMM_SMEM);
    cudaFuncSetAttribute(mma_gemm<0,1>,
                         cudaFuncAttributeMaxDynamicSharedMemorySize, GEMM_SMEM);
    cudaFuncSetAttribute(mma_gemm<1,0>,
                         cudaFuncAttributeMaxDynamicSharedMemorySize, GEMM_SMEM);

    cudaMemcpyAsync(x, x_in, (size_t)MTOT * DD * sizeof(float),
                    cudaMemcpyDeviceToDevice, 0);

    // ---- fused prep: all weight transposes + bias packing, one launch ----
    prep_kernel<<<PREP_BLOCKS, 256>>>(wq, wk, wv, wo, w1, w2, bq, bk, bv,
                                      pqkvT, poT, pw1T, pw2T, pbqkv);

    dim3 blk(256);
    dim3 gqkv(D3 / 128, MTOT / 128);  // (12, 32)
    dim3 gp(DD / 128, MTOT / 128);    // (4, 32)
    dim3 g1(D2 / 128, MTOT / 128);    // (8, 32)
    dim3 gfl(LL / 128, BB * HH);      // (16, 16)

    for (int l = 0; l < NLAYERS; l++) {
        // ---- attention block ----
        ln_kernel<<<MTOT, blk>>>(x, ln_ag + l * DD, ln_ab + l * DD, ph);
        mma_gemm<0,0><<<gqkv, blk, GEMM_SMEM>>>(
            ph, DD, pqkvT + (size_t)l * D3 * DD, DD, pbqkv + l * D3,
            nullptr, pqkv, D3, DD);
        flash_kernel<<<gfl, blk, FLASH_SMEM>>>(pqkv, mask, pctx);
        mma_gemm<0,1><<<gp, blk, GEMM_SMEM>>>(
            pctx, DD, poT + (size_t)l * DD * DD, DD, bo + l * DD, x, x, DD, DD);

        // ---- FFN block ----
        ln_kernel<<<MTOT, blk>>>(x, ln_fg + l * DD, ln_fb + l * DD, ph);
        mma_gemm<1,0><<<g1, blk, GEMM_SMEM>>>(
            ph, DD, pw1T + (size_t)l * D2 * DD, DD, b1 + l * D2,
            nullptr, pffn, D2, DD);
        mma_gemm<0,1><<<gp, blk, GEMM_SMEM>>>(
            pffn, D2, pw2T + (size_t)l * DD * D2, D2, b2 + l * DD, x, x, DD, D2);
    }
}

// round 7
// speedup vs baseline: 4.7280x; 1.1466x over previous
#include <cuda_runtime.h>
#include <cuda_bf16.h>
#include <math.h>

#define BB 2
#define LL 2048
#define DD 512
#define HH 8
#define DHH 64
#define NLAYERS 3
#define D2 1024
#define MTOT (BB * LL)          // 4096 rows
#define D3 1536
#define EPS 1e-5f

// ---------------- scratch (device globals; no allocations allowed) ----------
__device__ float g_h   [MTOT * DD];
__device__ float g_qkv [(size_t)MTOT * D3];
__device__ float g_ctx [MTOT * DD];
__device__ float g_ffn [MTOT * D2];
// transposed weights (row-major [N][K]) + packed qkv bias
__device__ float g_qkvT[(size_t)NLAYERS * D3 * DD];
__device__ float g_oT  [(size_t)NLAYERS * DD * DD];
__device__ float g_w1T [(size_t)NLAYERS * D2 * DD];
__device__ float g_w2T [(size_t)NLAYERS * DD * D2];
__device__ float g_bqkv[NLAYERS * D3];

// mma.tf32 truncates fp32 operand mantissas in HW -> feed raw fp32 bits.
__device__ __forceinline__ void mma_tf32(float* c, const unsigned* a,
                                         unsigned b0, unsigned b1) {
    asm volatile(
        "mma.sync.aligned.m16n8k8.row.col.f32.tf32.tf32.f32 "
        "{%0,%1,%2,%3}, {%4,%5,%6,%7}, {%8,%9}, {%0,%1,%2,%3};"
        : "+f"(c[0]), "+f"(c[1]), "+f"(c[2]), "+f"(c[3])
        : "r"(a[0]), "r"(a[1]), "r"(a[2]), "r"(a[3]), "r"(b0), "r"(b1));
}

__device__ __forceinline__ void ldsm4(unsigned* r, unsigned addr) {
    asm volatile("ldmatrix.sync.aligned.m8n8.x4.shared.b16 {%0,%1,%2,%3}, [%4];"
                 : "=r"(r[0]), "=r"(r[1]), "=r"(r[2]), "=r"(r[3]) : "r"(addr));
}

__device__ __forceinline__ unsigned sptr(const void* p) {
    return (unsigned)__cvta_generic_to_shared(p);
}

__device__ __forceinline__ void cpa16(unsigned dst, const void* src) {
    asm volatile("cp.async.cg.shared.global [%0], [%1], 16;" :: "r"(dst), "l"(src));
}

// ---------------- fused prep: ALL weight transposes + bias packing ---------
// 6144 tile blocks (2048/layer) + 18 bias blocks. One launch per replay.
#define PREP_BLOCKS (6144 + 18)
__global__ __launch_bounds__(256)
void prep_kernel(const float* __restrict__ wq, const float* __restrict__ wk,
                 const float* __restrict__ wv, const float* __restrict__ wo,
                 const float* __restrict__ w1, const float* __restrict__ w2,
                 const float* __restrict__ bq, const float* __restrict__ bk,
                 const float* __restrict__ bv,
                 float* __restrict__ qkvT, float* __restrict__ oT,
                 float* __restrict__ w1T, float* __restrict__ w2T,
                 float* __restrict__ bqkv)
{
    int bid = blockIdx.x;
    if (bid >= 6144) {                       // bias packing tail
        int gi = (bid - 6144) * 256 + threadIdx.x;
        if (gi < NLAYERS * D3) {
            int l = gi / D3, p = gi % D3;
            float v = (p < 512) ? bq[l * DD + p]
                    : (p < 1024) ? bk[l * DD + p - 512]
                                 : bv[l * DD + p - 1024];
            bqkv[gi] = v;
        }
        return;
    }
    int l = bid / 2048, seg = bid % 2048;
    const float* src; float* dst; int R, C, gx, gy;
    if (seg < 1024) {                        // 512x512 transposes
        int which = seg >> 8, t = seg & 255;
        R = DD; C = DD; gx = t & 15; gy = t >> 4;
        if (which == 0)      { src = wq + (size_t)l*DD*DD; dst = qkvT + (size_t)l*D3*DD; }
        else if (which == 1) { src = wk + (size_t)l*DD*DD; dst = qkvT + (size_t)l*D3*DD + (size_t)DD*DD; }
        else if (which == 2) { src = wv + (size_t)l*DD*DD; dst = qkvT + (size_t)l*D3*DD + (size_t)2*DD*DD; }
        else                 { src = wo + (size_t)l*DD*DD; dst = oT   + (size_t)l*DD*DD; }
    } else if (seg < 1536) {                 // w1 [512][1024]
        int t = seg - 1024;
        R = DD; C = D2; gx = t & 31; gy = t >> 5;
        src = w1 + (size_t)l*DD*D2; dst = w1T + (size_t)l*D2*DD;
    } else {                                 // w2 [1024][512]
        int t = seg - 1536;
        R = D2; C = DD; gx = t & 15; gy = t >> 4;
        src = w2 + (size_t)l*D2*DD; dst = w2T + (size_t)l*DD*D2;
    }
    __shared__ float s[32][33];
    int tx = threadIdx.x & 31, ty = threadIdx.x >> 5;
    int x = gx * 32 + tx, y = gy * 32 + ty;
    #pragma unroll
    for (int j = 0; j < 32; j += 8)
        s[ty + j][tx] = src[(size_t)(y + j) * C + x];
    __syncthreads();
    int x2 = gy * 32 + tx, y2 = gx * 32 + ty;
    #pragma unroll
    for (int j = 0; j < 32; j += 8)
        dst[(size_t)(y2 + j) * R + x2] = s[tx][ty + j];
}

// ---------------- LayerNorm: one block per row (D=512), 256 threads --------
__global__ __launch_bounds__(256)
void ln_kernel(const float* __restrict__ x, const float* __restrict__ g,
               const float* __restrict__ b, float* __restrict__ out) {
    int row = blockIdx.x;
    const float* xr = x + (size_t)row * DD;
    float*       orow = out + (size_t)row * DD;
    int t = threadIdx.x;
    float v0 = xr[t], v1 = xr[t + 256];
    float s  = v0 + v1;
    float sq = v0 * v0 + v1 * v1;

    __shared__ float red[8], red2[8];
    for (int o = 16; o > 0; o >>= 1) {
        s  += __shfl_down_sync(0xffffffffu, s,  o);
        sq += __shfl_down_sync(0xffffffffu, sq, o);
    }
    int warp = t >> 5, lane = t & 31;
    if (lane == 0) { red[warp] = s; red2[warp] = sq; }
    __syncthreads();
    __shared__ float s_mean, s_inv;
    if (t == 0) {
        float ts = 0.f, tq = 0.f;
        #pragma unroll
        for (int i = 0; i < 8; i++) { ts += red[i]; tq += red2[i]; }
        float mean = ts * (1.0f / DD);
        float var  = tq * (1.0f / DD) - mean * mean;
        s_mean = mean;
        s_inv  = rsqrtf(var + EPS);
    }
    __syncthreads();
    float mean = s_mean, inv = s_inv;
    orow[t]       = (v0 - mean) * inv * g[t]       + b[t];
    orow[t + 256] = (v1 - mean) * inv * g[t + 256] + b[t + 256];
}

// ---------------- tf32 ldmatrix tensor-core GEMM ---------------------------
// C = A @ Bt^T + bias [+res] [relu].  A row-major MxK, Bt row-major NxK.
// CTA 128x128x32, 256 threads (2x4 warps of 64x32), 3-stage cp.async pipeline.
// smem layout per operand: [row][8 chunks of 16B], chunk swizzled (c^row)&7.
#define GEMM_SMEM (3 * (128 + 128) * 32 * 4)
template<int RELU, int RES>
__global__ __launch_bounds__(256)
void mma_gemm(const float* __restrict__ A, int lda,
              const float* __restrict__ Bt, int ldb,
              const float* __restrict__ bias,
              const float* __restrict__ res,
              float* __restrict__ C, int ldc, int K)
{
    constexpr int BM = 128, BN = 128, BK = 32;
    constexpr int AW = BM * BK;   // words per A buffer
    constexpr int BW = BN * BK;
    extern __shared__ unsigned gsm[];
    unsigned* As = gsm;           // [3][128*32]
    unsigned* Bs = gsm + 3 * AW;  // [3][128*32]

    const int tid  = threadIdx.x;
    const int lane = tid & 31, warp = tid >> 5;
    const int g    = lane >> 2, tg = lane & 3;
    const int sub  = lane >> 3, rr = lane & 7;
    const int mW   = (warp >> 2) * 64, nW = (warp & 3) * 32;

    const int rowBase = blockIdx.y * BM;
    const int colBase = blockIdx.x * BN;
    const float* Ab  = A  + (size_t)rowBase * lda;
    const float* Btb = Bt + (size_t)colBase * ldb;
    float* Cb = C + (size_t)rowBase * ldc + colBase;

    // ldmatrix lane geometry
    const int aRow0 = (sub & 1) * 8 + rr;       // + mW + mt*16
    const int aClS  = sub >> 1;
    const int bRow0 = (sub >> 1) * 8 + rr;      // + nW + p*16
    const int bClS  = sub & 1;

    const unsigned aBase = sptr(As);
    const unsigned bBase = sptr(Bs);

    float acc[4][4][4];
    #pragma unroll
    for (int i = 0; i < 4; i++)
        #pragma unroll
        for (int j = 0; j < 4; j++)
            #pragma unroll
            for (int r = 0; r < 4; r++) acc[i][j][r] = 0.f;

    auto stage = [&](int kt, int buf) {
        const int k0 = kt * BK;
        unsigned* ad = As + buf * AW;
        unsigned* bd = Bs + buf * BW;
        #pragma unroll
        for (int i = 0; i < 4; i++) {
            int idx = i * 256 + tid;
            int row = idx >> 3, c = idx & 7;
            cpa16(sptr(ad + (row * 8 + ((c ^ row) & 7)) * 4),
                  Ab + (size_t)row * lda + k0 + c * 4);
        }
        #pragma unroll
        for (int i = 0; i < 4; i++) {
            int idx = i * 256 + tid;
            int n = idx >> 3, c = idx & 7;
            cpa16(sptr(bd + (n * 8 + ((c ^ n) & 7)) * 4),
                  Btb + (size_t)n * ldb + k0 + c * 4);
        }
        asm volatile("cp.async.commit_group;");
    };

    const int KT = K / BK;
    stage(0, 0);
    if (KT > 1) stage(1, 1);

    for (int kt = 0; kt < KT; kt++) {
        const int buf = kt % 3;
        if (kt + 1 < KT) asm volatile("cp.async.wait_group 1;");
        else             asm volatile("cp.async.wait_group 0;");
        __syncthreads();

        const unsigned aB = aBase + buf * AW * 4;
        const unsigned bB = bBase + buf * BW * 4;
        #pragma unroll
        for (int ksi = 0; ksi < 4; ksi++) {
            const int clb = ksi * 2;
            unsigned af[4][4], bf[2][4];
            #pragma unroll
            for (int mt = 0; mt < 4; mt++) {
                int row = mW + mt * 16 + aRow0;
                int cl  = clb + aClS;
                ldsm4(af[mt], aB + ((row * 8 + ((cl ^ row) & 7)) << 4));
            }
            #pragma unroll
            for (int p = 0; p < 2; p++) {
                int row = nW + p * 16 + bRow0;
                int cl  = clb + bClS;
                ldsm4(bf[p], bB + ((row * 8 + ((cl ^ row) & 7)) << 4));
            }
            #pragma unroll
            for (int mt = 0; mt < 4; mt++)
                #pragma unroll
                for (int nt = 0; nt < 4; nt++)
                    mma_tf32(acc[mt][nt], af[mt],
                             bf[nt >> 1][(nt & 1) * 2], bf[nt >> 1][(nt & 1) * 2 + 1]);
        }

        if (kt + 2 < KT) stage(kt + 2, (kt + 2) % 3);
        __syncthreads();
    }

    // epilogue
    #pragma unroll
    for (int mt = 0; mt < 4; mt++) {
        int r0 = mW + mt * 16 + g;
        #pragma unroll
        for (int nt = 0; nt < 4; nt++) {
            int c = nW + nt * 8 + 2 * tg;
            float2 bi = *(const float2*)(bias + colBase + c);
            float2 o0, o1;
            o0.x = acc[mt][nt][0] + bi.x; o0.y = acc[mt][nt][1] + bi.y;
            o1.x = acc[mt][nt][2] + bi.x; o1.y = acc[mt][nt][3] + bi.y;
            if (RES) {
                const float* rb = res + (size_t)rowBase * ldc + colBase;
                float2 q0 = *(const float2*)(rb + (size_t)r0 * ldc + c);
                float2 q1 = *(const float2*)(rb + (size_t)(r0 + 8) * ldc + c);
                o0.x += q0.x; o0.y += q0.y; o1.x += q1.x; o1.y += q1.y;
            }
            if (RELU) {
                o0.x = fmaxf(o0.x, 0.f); o0.y = fmaxf(o0.y, 0.f);
                o1.x = fmaxf(o1.x, 0.f); o1.y = fmaxf(o1.y, 0.f);
            }
            *(float2*)(Cb + (size_t)r0 * ldc + c) = o0;
            *(float2*)(Cb + (size_t)(r0 + 8) * ldc + c) = o1;
        }
    }
}

// ---------------- Flash attention ------------------------------------------
// grid = (L/128 q-tiles, B*H). 256 threads, warp owns 16 q-rows.
// Reads packed QKV [4096][1536]: q at +0, k at +512, v at +1024.
// __launch_bounds__(256,2): cap regs at 128 so 2 CTAs/SM are resident
// (Q fragments reloaded from smem per k-group instead of living in regs).
#define FQ_WORDS (128 * 64)
#define FK_WORDS (64 * 64)
#define FV_WORDS (64 * 72)
#define FLASH_SMEM ((FQ_WORDS + 2 * FK_WORDS + 2 * FV_WORDS + LL) * 4)

__global__ __launch_bounds__(256, 2)
void flash_kernel(const float* __restrict__ qkv,
                  const unsigned char* __restrict__ mask,
                  float* __restrict__ ctx)
{
    extern __shared__ unsigned fsm[];
    unsigned* Qs = fsm;                         // [128][16 chunks] swizzled
    unsigned* Ks = Qs + FQ_WORDS;               // [2][64][16 chunks] swizzled
    unsigned* Vs = Ks + 2 * FK_WORDS;           // [2][64][72] plain
    float*    Ms = (float*)(Vs + 2 * FV_WORDS); // [2048] 0 / -inf

    const int tid  = threadIdx.x;
    const int lane = tid & 31, warp = tid >> 5;
    const int g    = lane >> 2, tg = lane & 3;
    const int sub  = lane >> 3, rr = lane & 7;
    const int bh   = blockIdx.y;
    const int b    = bh >> 3, h = bh & 7;
    const int q0   = blockIdx.x * 128;
    const int mW   = warp * 16;

    const float* qb = qkv + ((size_t)b * LL + q0) * D3 + h * DHH;
    const float* kb = qkv + (size_t)b * LL * D3 + 512  + h * DHH;
    const float* vb = qkv + (size_t)b * LL * D3 + 1024 + h * DHH;

    auto loadKV = [&](int tile, int buf) {
        int key0 = tile * 64;
        unsigned* kd = Ks + buf * FK_WORDS;
        unsigned* vd = Vs + buf * FV_WORDS;
        #pragma unroll
        for (int i = 0; i < 4; i++) {
            int idx = tid + i * 256;
            int row = idx >> 4, c = idx & 15;
            const float* sk = kb + (size_t)(key0 + row) * D3 + c * 4;
            const float* sv = vb + (size_t)(key0 + row) * D3 + c * 4;
            cpa16(sptr(kd + (row * 16 + ((c & 8) | ((c ^ row) & 7))) * 4), sk);
            cpa16(sptr(vd + row * 72 + c * 4), sv);
        }
        asm volatile("cp.async.commit_group;");
    };

    loadKV(0, 0);
    loadKV(1, 1);

    // Q tile -> swizzled smem (raw bits), mask -> smem
    #pragma unroll
    for (int i = 0; i < 8; i++) {
        int idx = tid + i * 256;
        int row = idx >> 4, c = idx & 15;
        float4 x = *(const float4*)(qb + (size_t)row * D3 + c * 4);
        uint4 u;
        u.x = __float_as_uint(x.x); u.y = __float_as_uint(x.y);
        u.z = __float_as_uint(x.z); u.w = __float_as_uint(x.w);
        *(uint4*)(Qs + (row * 16 + ((c & 8) | ((c ^ row) & 7))) * 4) = u;
    }
    const unsigned char* mrow = mask + (size_t)b * LL;
    #pragma unroll
    for (int i = 0; i < 8; i++) {
        int idx = tid + i * 256;
        Ms[idx] = mrow[idx] ? -INFINITY : 0.f;
    }
    __syncthreads();

    const unsigned qBase = sptr(Qs);
    const unsigned kBase = sptr(Ks);
    // per-thread Q ldmatrix address pieces (recomputed fragment loads per kg)
    const int qRow = mW + (sub & 1) * 8 + rr;
    const int qClS = sub >> 1;

    float m0 = -1e30f, m1 = -1e30f, l0 = 0.f, l1 = 0.f;
    float o[8][4];
    #pragma unroll
    for (int nt = 0; nt < 8; nt++)
        #pragma unroll
        for (int j = 0; j < 4; j++) o[nt][j] = 0.f;

    const int srcA = (lane & ~3) | (tg >> 1);
    const int srcB = srcA + 2;

    for (int t = 0; t < LL / 64; t++) {
        const int buf = t & 1;
        if (t == LL / 64 - 1) asm volatile("cp.async.wait_group 0;");
        else                  asm volatile("cp.async.wait_group 1;");
        __syncthreads();

        const unsigned kB = kBase + buf * FK_WORDS * 4;
        const unsigned* Vb = Vs + buf * FV_WORDS;

        // S = Q @ K^T  (warp: 16 x 64); Q fragment reloaded per k-group
        float s[8][4];
        #pragma unroll
        for (int nt = 0; nt < 8; nt++)
            #pragma unroll
            for (int j = 0; j < 4; j++) s[nt][j] = 0.f;
        #pragma unroll
        for (int kg = 0; kg < 8; kg++) {
            unsigned qf[4];
            {
                int cl = 2 * kg + qClS;
                ldsm4(qf, qBase + ((qRow * 16 + ((cl & 8) | ((cl ^ qRow) & 7))) << 4));
            }
            unsigned kf[4][4];
            #pragma unroll
            for (int p = 0; p < 4; p++) {
                int row = 16 * p + (sub >> 1) * 8 + rr;
                int cl  = 2 * kg + (sub & 1);
                ldsm4(kf[p], kB + ((row * 16 + ((cl & 8) | ((cl ^ row) & 7))) << 4));
            }
            #pragma unroll
            for (int nt = 0; nt < 8; nt++)
                mma_tf32(s[nt], qf,
                         kf[nt >> 1][(nt & 1) * 2], kf[nt >> 1][(nt & 1) * 2 + 1]);
        }

        // scale + mask + online softmax
        const int key0 = t * 64;
        float rm0 = -INFINITY, rm1 = -INFINITY;
        #pragma unroll
        for (int nt = 0; nt < 8; nt++) {
            float ma = Ms[key0 + 8 * nt + 2 * tg];
            float mb = Ms[key0 + 8 * nt + 2 * tg + 1];
            s[nt][0] = s[nt][0] * 0.125f + ma;
            s[nt][1] = s[nt][1] * 0.125f + mb;
            s[nt][2] = s[nt][2] * 0.125f + ma;
            s[nt][3] = s[nt][3] * 0.125f + mb;
            rm0 = fmaxf(rm0, fmaxf(s[nt][0], s[nt][1]));
            rm1 = fmaxf(rm1, fmaxf(s[nt][2], s[nt][3]));
        }
        rm0 = fmaxf(rm0, __shfl_xor_sync(0xffffffffu, rm0, 1));
        rm0 = fmaxf(rm0, __shfl_xor_sync(0xffffffffu, rm0, 2));
        rm1 = fmaxf(rm1, __shfl_xor_sync(0xffffffffu, rm1, 1));
        rm1 = fmaxf(rm1, __shfl_xor_sync(0xffffffffu, rm1, 2));

        float mn0 = fmaxf(m0, rm0), mn1 = fmaxf(m1, rm1);
        float al0 = __expf(m0 - mn0), al1 = __expf(m1 - mn1);
        float sum0 = 0.f, sum1 = 0.f;
        #pragma unroll
        for (int nt = 0; nt < 8; nt++) {
            s[nt][0] = __expf(s[nt][0] - mn0);
            s[nt][1] = __expf(s[nt][1] - mn0);
            s[nt][2] = __expf(s[nt][2] - mn1);
            s[nt][3] = __expf(s[nt][3] - mn1);
            sum0 += s[nt][0] + s[nt][1];
            sum1 += s[nt][2] + s[nt][3];
        }
        sum0 += __shfl_xor_sync(0xffffffffu, sum0, 1);
        sum0 += __shfl_xor_sync(0xffffffffu, sum0, 2);
        sum1 += __shfl_xor_sync(0xffffffffu, sum1, 1);
        sum1 += __shfl_xor_sync(0xffffffffu, sum1, 2);
        l0 = l0 * al0 + sum0; l1 = l1 * al1 + sum1;
        m0 = mn0; m1 = mn1;
        #pragma unroll
        for (int nt = 0; nt < 8; nt++) {
            o[nt][0] *= al0; o[nt][1] *= al0;
            o[nt][2] *= al1; o[nt][3] *= al1;
        }

        // O += P @ V : shuffle P (accumulator layout) into A-fragment layout
        #pragma unroll
        for (int kg = 0; kg < 8; kg++) {
            float w0, w1;
            unsigned a[4];
            w0 = __shfl_sync(0xffffffffu, s[kg][0], srcA);
            w1 = __shfl_sync(0xffffffffu, s[kg][1], srcA);
            a[0] = __float_as_uint((tg & 1) ? w1 : w0);
            w0 = __shfl_sync(0xffffffffu, s[kg][2], srcA);
            w1 = __shfl_sync(0xffffffffu, s[kg][3], srcA);
            a[1] = __float_as_uint((tg & 1) ? w1 : w0);
            w0 = __shfl_sync(0xffffffffu, s[kg][0], srcB);
            w1 = __shfl_sync(0xffffffffu, s[kg][1], srcB);
            a[2] = __float_as_uint((tg & 1) ? w1 : w0);
            w0 = __shfl_sync(0xffffffffu, s[kg][2], srcB);
            w1 = __shfl_sync(0xffffffffu, s[kg][3], srcB);
            a[3] = __float_as_uint((tg & 1) ? w1 : w0);
            #pragma unroll
            for (int nt = 0; nt < 8; nt++) {
                unsigned b0 = Vb[(8 * kg + tg)     * 72 + 8 * nt + g];
                unsigned b1 = Vb[(8 * kg + tg + 4) * 72 + 8 * nt + g];
                mma_tf32(o[nt], a, b0, b1);
            }
        }
        __syncthreads();
        if (t + 2 < LL / 64) loadKV(t + 2, buf);
    }

    // normalize + write ctx
    float i0 = 1.f / l0, i1 = 1.f / l1;
    float* cb = ctx + ((size_t)b * LL + q0 + mW) * DD + h * DHH;
    #pragma unroll
    for (int nt = 0; nt < 8; nt++) {
        int c = 8 * nt + 2 * tg;
        float2 u0, u1;
        u0.x = o[nt][0] * i0; u0.y = o[nt][1] * i0;
        u1.x = o[nt][2] * i1; u1.y = o[nt][3] * i1;
        *(float2*)(cb + (size_t)g * DD + c) = u0;
        *(float2*)(cb + (size_t)(g + 8) * DD + c) = u1;
    }
}

// ---------------------------------------------------------------------------
extern "C" void kernel_launch(void* const* d_in, const int* in_sizes, int n_in,
                              void* d_out, int out_size) {
    (void)in_sizes; (void)n_in; (void)out_size;
    const float* x_in  = (const float*)d_in[0];
    const unsigned char* mask = (const unsigned char*)d_in[1];
    const float* ln_ag = (const float*)d_in[2];
    const float* ln_ab = (const float*)d_in[3];
    const float* wq = (const float*)d_in[4];
    const float* bq = (const float*)d_in[5];
    const float* wk = (const float*)d_in[6];
    const float* bk = (const float*)d_in[7];
    const float* wv = (const float*)d_in[8];
    const float* bv = (const float*)d_in[9];
    const float* wo = (const float*)d_in[10];
    const float* bo = (const float*)d_in[11];
    const float* ln_fg = (const float*)d_in[12];
    const float* ln_fb = (const float*)d_in[13];
    const float* w1 = (const float*)d_in[14];
    const float* b1 = (const float*)d_in[15];
    const float* w2 = (const float*)d_in[16];
    const float* b2 = (const float*)d_in[17];

    float* x = (float*)d_out;   // residual stream lives in the output buffer

    float *ph, *pqkv, *pctx, *pffn, *pqkvT, *poT, *pw1T, *pw2T, *pbqkv;
    cudaGetSymbolAddress((void**)&ph,    g_h);
    cudaGetSymbolAddress((void**)&pqkv,  g_qkv);
    cudaGetSymbolAddress((void**)&pctx,  g_ctx);
    cudaGetSymbolAddress((void**)&pffn,  g_ffn);
    cudaGetSymbolAddress((void**)&pqkvT, g_qkvT);
    cudaGetSymbolAddress((void**)&poT,   g_oT);
    cudaGetSymbolAddress((void**)&pw1T,  g_w1T);
    cudaGetSymbolAddress((void**)&pw2T,  g_w2T);
    cudaGetSymbolAddress((void**)&pbqkv, g_bqkv);

    cudaFuncSetAttribute(flash_kernel,
                         cudaFuncAttributeMaxDynamicSharedMemorySize, FLASH_SMEM);
    cudaFuncSetAttribute(mma_gemm<0,0>,
                         cudaFuncAttributeMaxDynamicSharedMemorySize, GEMM_SMEM);
    cudaFuncSetAttribute(mma_gemm<0,1>,
                         cudaFuncAttributeMaxDynamicSharedMemorySize, GEMM_SMEM);
    cudaFuncSetAttribute(mma_gemm<1,0>,
                         cudaFuncAttributeMaxDynamicSharedMemorySize, GEMM_SMEM);

    cudaMemcpyAsync(x, x_in, (size_t)MTOT * DD * sizeof(float),
                    cudaMemcpyDeviceToDevice, 0);

    // ---- fused prep: all weight transposes + bias packing, one launch ----
    prep_kernel<<<PREP_BLOCKS, 256>>>(wq, wk, wv, wo, w1, w2, bq, bk, bv,
                                      pqkvT, poT, pw1T, pw2T, pbqkv);

    dim3 blk(256);
    dim3 gqkv(D3 / 128, MTOT / 128);  // (12, 32)
    dim3 gp(DD / 128, MTOT / 128);    // (4, 32)
    dim3 g1(D2 / 128, MTOT / 128);    // (8, 32)
    dim3 gfl(LL / 128, BB * HH);      // (16, 16)

    for (int l = 0; l < NLAYERS; l++) {
        // ---- attention block ----
        ln_kernel<<<MTOT, blk>>>(x, ln_ag + l * DD, ln_ab + l * DD, ph);
        mma_gemm<0,0><<<gqkv, blk, GEMM_SMEM>>>(
            ph, DD, pqkvT + (size_t)l * D3 * DD, DD, pbqkv + l * D3,
            nullptr, pqkv, D3, DD);
        flash_kernel<<<gfl, blk, FLASH_SMEM>>>(pqkv, mask, pctx);
        mma_gemm<0,1><<<gp, blk, GEMM_SMEM>>>(
            pctx, DD, poT + (size_t)l * DD * DD, DD, bo + l * DD, x, x, DD, DD);

        // ---- FFN block ----
        ln_kernel<<<MTOT, blk>>>(x, ln_fg + l * DD, ln_fb + l * DD, ph);
        mma_gemm<1,0><<<g1, blk, GEMM_SMEM>>>(
            ph, DD, pw1T + (size_t)l * D2 * DD, DD, b1 + l * D2,
            nullptr, pffn, D2, DD);
        mma_gemm<0,1><<<gp, blk, GEMM_SMEM>>>(
            pffn, D2, pw2T + (size_t)l * DD * D2, D2, b2 + l * DD, x, x, DD, D2);
    }
}

// round 8
// speedup vs baseline: 5.0963x; 1.0779x over previous
#include <cuda_runtime.h>
#include <cuda_bf16.h>
#include <math.h>

#define BB 2
#define LL 2048
#define DD 512
#define HH 8
#define DHH 64
#define NLAYERS 3
#define D2 1024
#define MTOT (BB * LL)          // 4096 rows
#define D3 1536
#define EPS 1e-5f

// ---------------- scratch (device globals; no allocations allowed) ----------
__device__ float g_h   [MTOT * DD];
__device__ float g_qkv [(size_t)MTOT * D3];
__device__ float g_vT  [(size_t)BB * DD * LL];   // V transposed: [b][h*64+d][key]
__device__ float g_ctx [MTOT * DD];
__device__ float g_ffn [MTOT * D2];
// transposed weights (row-major [N][K]) + packed qkv bias
__device__ float g_qkvT[(size_t)NLAYERS * D3 * DD];
__device__ float g_oT  [(size_t)NLAYERS * DD * DD];
__device__ float g_w1T [(size_t)NLAYERS * D2 * DD];
__device__ float g_w2T [(size_t)NLAYERS * DD * D2];
__device__ float g_bqkv[NLAYERS * D3];

// mma.tf32 truncates fp32 operand mantissas in HW -> feed raw fp32 bits.
__device__ __forceinline__ void mma_tf32(float* c, const unsigned* a,
                                         unsigned b0, unsigned b1) {
    asm volatile(
        "mma.sync.aligned.m16n8k8.row.col.f32.tf32.tf32.f32 "
        "{%0,%1,%2,%3}, {%4,%5,%6,%7}, {%8,%9}, {%0,%1,%2,%3};"
        : "+f"(c[0]), "+f"(c[1]), "+f"(c[2]), "+f"(c[3])
        : "r"(a[0]), "r"(a[1]), "r"(a[2]), "r"(a[3]), "r"(b0), "r"(b1));
}

__device__ __forceinline__ void ldsm4(unsigned* r, unsigned addr) {
    asm volatile("ldmatrix.sync.aligned.m8n8.x4.shared.b16 {%0,%1,%2,%3}, [%4];"
                 : "=r"(r[0]), "=r"(r[1]), "=r"(r[2]), "=r"(r[3]) : "r"(addr));
}

__device__ __forceinline__ unsigned sptr(const void* p) {
    return (unsigned)__cvta_generic_to_shared(p);
}

__device__ __forceinline__ void cpa16(unsigned dst, const void* src) {
    asm volatile("cp.async.cg.shared.global [%0], [%1], 16;" :: "r"(dst), "l"(src));
}

// ---------------- fused prep: ALL weight transposes + bias packing ---------
#define PREP_BLOCKS (6144 + 18)
__global__ __launch_bounds__(256)
void prep_kernel(const float* __restrict__ wq, const float* __restrict__ wk,
                 const float* __restrict__ wv, const float* __restrict__ wo,
                 const float* __restrict__ w1, const float* __restrict__ w2,
                 const float* __restrict__ bq, const float* __restrict__ bk,
                 const float* __restrict__ bv,
                 float* __restrict__ qkvT, float* __restrict__ oT,
                 float* __restrict__ w1T, float* __restrict__ w2T,
                 float* __restrict__ bqkv)
{
    int bid = blockIdx.x;
    if (bid >= 6144) {                       // bias packing tail
        int gi = (bid - 6144) * 256 + threadIdx.x;
        if (gi < NLAYERS * D3) {
            int l = gi / D3, p = gi % D3;
            float v = (p < 512) ? bq[l * DD + p]
                    : (p < 1024) ? bk[l * DD + p - 512]
                                 : bv[l * DD + p - 1024];
            bqkv[gi] = v;
        }
        return;
    }
    int l = bid / 2048, seg = bid % 2048;
    const float* src; float* dst; int R, C, gx, gy;
    if (seg < 1024) {                        // 512x512 transposes
        int which = seg >> 8, t = seg & 255;
        R = DD; C = DD; gx = t & 15; gy = t >> 4;
        if (which == 0)      { src = wq + (size_t)l*DD*DD; dst = qkvT + (size_t)l*D3*DD; }
        else if (which == 1) { src = wk + (size_t)l*DD*DD; dst = qkvT + (size_t)l*D3*DD + (size_t)DD*DD; }
        else if (which == 2) { src = wv + (size_t)l*DD*DD; dst = qkvT + (size_t)l*D3*DD + (size_t)2*DD*DD; }
        else                 { src = wo + (size_t)l*DD*DD; dst = oT   + (size_t)l*DD*DD; }
    } else if (seg < 1536) {                 // w1 [512][1024]
        int t = seg - 1024;
        R = DD; C = D2; gx = t & 31; gy = t >> 5;
        src = w1 + (size_t)l*DD*D2; dst = w1T + (size_t)l*D2*DD;
    } else {                                 // w2 [1024][512]
        int t = seg - 1536;
        R = D2; C = DD; gx = t & 15; gy = t >> 4;
        src = w2 + (size_t)l*D2*DD; dst = w2T + (size_t)l*DD*D2;
    }
    __shared__ float s[32][33];
    int tx = threadIdx.x & 31, ty = threadIdx.x >> 5;
    int x = gx * 32 + tx, y = gy * 32 + ty;
    #pragma unroll
    for (int j = 0; j < 32; j += 8)
        s[ty + j][tx] = src[(size_t)(y + j) * C + x];
    __syncthreads();
    int x2 = gy * 32 + tx, y2 = gx * 32 + ty;
    #pragma unroll
    for (int j = 0; j < 32; j += 8)
        dst[(size_t)(y2 + j) * R + x2] = s[tx][ty + j];
}

// ---------------- per-layer V transpose: vT[b][d][key] = V[b][key][d] ------
// grid (LL/32, DD/32, BB), 256 threads
__global__ __launch_bounds__(256)
void vtrans_kernel(const float* __restrict__ qkv, float* __restrict__ vT) {
    __shared__ float s[32][33];
    int key0 = blockIdx.x * 32, d0 = blockIdx.y * 32, b = blockIdx.z;
    int tx = threadIdx.x & 31, ty = threadIdx.x >> 5;
    const float* src = qkv + ((size_t)b * LL + key0) * D3 + 1024 + d0;
    #pragma unroll
    for (int j = 0; j < 32; j += 8)
        s[ty + j][tx] = src[(size_t)(ty + j) * D3 + tx];
    __syncthreads();
    float* dst = vT + ((size_t)b * DD + d0) * LL + key0;
    #pragma unroll
    for (int j = 0; j < 32; j += 8)
        dst[(size_t)(ty + j) * LL + tx] = s[tx][ty + j];
}

// ---------------- LayerNorm: one block per row (D=512), 256 threads --------
__global__ __launch_bounds__(256)
void ln_kernel(const float* __restrict__ x, const float* __restrict__ g,
               const float* __restrict__ b, float* __restrict__ out) {
    int row = blockIdx.x;
    const float* xr = x + (size_t)row * DD;
    float*       orow = out + (size_t)row * DD;
    int t = threadIdx.x;
    float v0 = xr[t], v1 = xr[t + 256];
    float s  = v0 + v1;
    float sq = v0 * v0 + v1 * v1;

    __shared__ float red[8], red2[8];
    for (int o = 16; o > 0; o >>= 1) {
        s  += __shfl_down_sync(0xffffffffu, s,  o);
        sq += __shfl_down_sync(0xffffffffu, sq, o);
    }
    int warp = t >> 5, lane = t & 31;
    if (lane == 0) { red[warp] = s; red2[warp] = sq; }
    __syncthreads();
    __shared__ float s_mean, s_inv;
    if (t == 0) {
        float ts = 0.f, tq = 0.f;
        #pragma unroll
        for (int i = 0; i < 8; i++) { ts += red[i]; tq += red2[i]; }
        float mean = ts * (1.0f / DD);
        float var  = tq * (1.0f / DD) - mean * mean;
        s_mean = mean;
        s_inv  = rsqrtf(var + EPS);
    }
    __syncthreads();
    float mean = s_mean, inv = s_inv;
    orow[t]       = (v0 - mean) * inv * g[t]       + b[t];
    orow[t + 256] = (v1 - mean) * inv * g[t + 256] + b[t + 256];
}

// ---------------- tf32 ldmatrix tensor-core GEMM ---------------------------
#define GEMM_SMEM (3 * (128 + 128) * 32 * 4)
template<int RELU, int RES>
__global__ __launch_bounds__(256)
void mma_gemm(const float* __restrict__ A, int lda,
              const float* __restrict__ Bt, int ldb,
              const float* __restrict__ bias,
              const float* __restrict__ res,
              float* __restrict__ C, int ldc, int K)
{
    constexpr int BM = 128, BN = 128, BK = 32;
    constexpr int AW = BM * BK;
    constexpr int BW = BN * BK;
    extern __shared__ unsigned gsm[];
    unsigned* As = gsm;
    unsigned* Bs = gsm + 3 * AW;

    const int tid  = threadIdx.x;
    const int lane = tid & 31, warp = tid >> 5;
    const int g    = lane >> 2, tg = lane & 3;
    const int sub  = lane >> 3, rr = lane & 7;
    const int mW   = (warp >> 2) * 64, nW = (warp & 3) * 32;

    const int rowBase = blockIdx.y * BM;
    const int colBase = blockIdx.x * BN;
    const float* Ab  = A  + (size_t)rowBase * lda;
    const float* Btb = Bt + (size_t)colBase * ldb;
    float* Cb = C + (size_t)rowBase * ldc + colBase;

    const int aRow0 = (sub & 1) * 8 + rr;
    const int aClS  = sub >> 1;
    const int bRow0 = (sub >> 1) * 8 + rr;
    const int bClS  = sub & 1;

    const unsigned aBase = sptr(As);
    const unsigned bBase = sptr(Bs);

    float acc[4][4][4];
    #pragma unroll
    for (int i = 0; i < 4; i++)
        #pragma unroll
        for (int j = 0; j < 4; j++)
            #pragma unroll
            for (int r = 0; r < 4; r++) acc[i][j][r] = 0.f;

    auto stage = [&](int kt, int buf) {
        const int k0 = kt * BK;
        unsigned* ad = As + buf * AW;
        unsigned* bd = Bs + buf * BW;
        #pragma unroll
        for (int i = 0; i < 4; i++) {
            int idx = i * 256 + tid;
            int row = idx >> 3, c = idx & 7;
            cpa16(sptr(ad + (row * 8 + ((c ^ row) & 7)) * 4),
                  Ab + (size_t)row * lda + k0 + c * 4);
        }
        #pragma unroll
        for (int i = 0; i < 4; i++) {
            int idx = i * 256 + tid;
            int n = idx >> 3, c = idx & 7;
            cpa16(sptr(bd + (n * 8 + ((c ^ n) & 7)) * 4),
                  Btb + (size_t)n * ldb + k0 + c * 4);
        }
        asm volatile("cp.async.commit_group;");
    };

    const int KT = K / BK;
    stage(0, 0);
    if (KT > 1) stage(1, 1);

    for (int kt = 0; kt < KT; kt++) {
        const int buf = kt % 3;
        if (kt + 1 < KT) asm volatile("cp.async.wait_group 1;");
        else             asm volatile("cp.async.wait_group 0;");
        __syncthreads();

        const unsigned aB = aBase + buf * AW * 4;
        const unsigned bB = bBase + buf * BW * 4;
        #pragma unroll
        for (int ksi = 0; ksi < 4; ksi++) {
            const int clb = ksi * 2;
            unsigned af[4][4], bf[2][4];
            #pragma unroll
            for (int mt = 0; mt < 4; mt++) {
                int row = mW + mt * 16 + aRow0;
                int cl  = clb + aClS;
                ldsm4(af[mt], aB + ((row * 8 + ((cl ^ row) & 7)) << 4));
            }
            #pragma unroll
            for (int p = 0; p < 2; p++) {
                int row = nW + p * 16 + bRow0;
                int cl  = clb + bClS;
                ldsm4(bf[p], bB + ((row * 8 + ((cl ^ row) & 7)) << 4));
            }
            #pragma unroll
            for (int mt = 0; mt < 4; mt++)
                #pragma unroll
                for (int nt = 0; nt < 4; nt++)
                    mma_tf32(acc[mt][nt], af[mt],
                             bf[nt >> 1][(nt & 1) * 2], bf[nt >> 1][(nt & 1) * 2 + 1]);
        }

        if (kt + 2 < KT) stage(kt + 2, (kt + 2) % 3);
        __syncthreads();
    }

    #pragma unroll
    for (int mt = 0; mt < 4; mt++) {
        int r0 = mW + mt * 16 + g;
        #pragma unroll
        for (int nt = 0; nt < 4; nt++) {
            int c = nW + nt * 8 + 2 * tg;
            float2 bi = *(const float2*)(bias + colBase + c);
            float2 o0, o1;
            o0.x = acc[mt][nt][0] + bi.x; o0.y = acc[mt][nt][1] + bi.y;
            o1.x = acc[mt][nt][2] + bi.x; o1.y = acc[mt][nt][3] + bi.y;
            if (RES) {
                const float* rb = res + (size_t)rowBase * ldc + colBase;
                float2 q0 = *(const float2*)(rb + (size_t)r0 * ldc + c);
                float2 q1 = *(const float2*)(rb + (size_t)(r0 + 8) * ldc + c);
                o0.x += q0.x; o0.y += q0.y; o1.x += q1.x; o1.y += q1.y;
            }
            if (RELU) {
                o0.x = fmaxf(o0.x, 0.f); o0.y = fmaxf(o0.y, 0.f);
                o1.x = fmaxf(o1.x, 0.f); o1.y = fmaxf(o1.y, 0.f);
            }
            *(float2*)(Cb + (size_t)r0 * ldc + c) = o0;
            *(float2*)(Cb + (size_t)(r0 + 8) * ldc + c) = o1;
        }
    }
}

// ---------------- Flash attention ------------------------------------------
// grid = (L/128 q-tiles, B*H). 128 threads (4 warps), warp owns 32 q-rows.
// V pre-transposed (g_vT) so PV uses ldmatrix B-fragments like QK.
// 104KB smem, __launch_bounds__(128,2): 2 CTAs/SM.
#define FQ_WORDS (128 * 64)
#define FK_WORDS (64 * 64)
#define FV_WORDS (64 * 64)
#define FLASH_SMEM ((FQ_WORDS + 2 * FK_WORDS + 2 * FV_WORDS + LL) * 4)

__global__ __launch_bounds__(128, 2)
void flash_kernel(const float* __restrict__ qkv,
                  const float* __restrict__ vT,
                  const unsigned char* __restrict__ mask,
                  float* __restrict__ ctx)
{
    extern __shared__ unsigned fsm[];
    unsigned* Qs = fsm;                         // [128][16 chunks] swizzled
    unsigned* Ks = Qs + FQ_WORDS;               // [2][64 keys][16 chunks] swizzled
    unsigned* Vs = Ks + 2 * FK_WORDS;           // [2][64 d-rows][16 key-chunks] swizzled
    float*    Ms = (float*)(Vs + 2 * FV_WORDS); // [2048] 0 / -inf

    const int tid  = threadIdx.x;
    const int lane = tid & 31, warp = tid >> 5;
    const int g    = lane >> 2, tg = lane & 3;
    const int sub  = lane >> 3, rr = lane & 7;
    const int bh   = blockIdx.y;
    const int b    = bh >> 3, h = bh & 7;
    const int q0   = blockIdx.x * 128;
    const int mW   = warp * 32;

    const float* qb  = qkv + ((size_t)b * LL + q0) * D3 + h * DHH;
    const float* kb  = qkv + (size_t)b * LL * D3 + 512 + h * DHH;
    const float* vtb = vT + ((size_t)b * DD + h * DHH) * LL;

    auto loadKV = [&](int tile, int buf) {
        int key0 = tile * 64;
        unsigned* kd = Ks + buf * FK_WORDS;
        unsigned* vd = Vs + buf * FV_WORDS;
        #pragma unroll
        for (int i = 0; i < 8; i++) {
            int idx = tid + i * 128;
            int row = idx >> 4, c = idx & 15;
            cpa16(sptr(kd + (row * 16 + ((c & 8) | ((c ^ row) & 7))) * 4),
                  kb + (size_t)(key0 + row) * D3 + c * 4);
        }
        #pragma unroll
        for (int i = 0; i < 8; i++) {
            int idx = tid + i * 128;
            int row = idx >> 4, c = idx & 15;   // row = d, c = key chunk
            cpa16(sptr(vd + (row * 16 + ((c & 8) | ((c ^ row) & 7))) * 4),
                  vtb + (size_t)row * LL + key0 + c * 4);
        }
        asm volatile("cp.async.commit_group;");
    };

    // Q tile via cp.async (group issued FIRST so wait_group 1 covers it)
    #pragma unroll
    for (int i = 0; i < 16; i++) {
        int idx = tid + i * 128;
        int row = idx >> 4, c = idx & 15;
        cpa16(sptr(Qs + (row * 16 + ((c & 8) | ((c ^ row) & 7))) * 4),
              qb + (size_t)row * D3 + c * 4);
    }
    asm volatile("cp.async.commit_group;");
    loadKV(0, 0);
    loadKV(1, 1);

    const unsigned char* mrow = mask + (size_t)b * LL;
    #pragma unroll
    for (int i = 0; i < 16; i++) {
        int idx = tid + i * 128;
        Ms[idx] = mrow[idx] ? -INFINITY : 0.f;
    }

    const unsigned qBase = sptr(Qs);
    const unsigned kBase = sptr(Ks);
    const unsigned vBase = sptr(Vs);

    float m[2][2], l[2][2];
    #pragma unroll
    for (int i = 0; i < 2; i++)
        #pragma unroll
        for (int j = 0; j < 2; j++) { m[i][j] = -1e30f; l[i][j] = 0.f; }
    float o[2][8][4];
    #pragma unroll
    for (int mt = 0; mt < 2; mt++)
        #pragma unroll
        for (int nt = 0; nt < 8; nt++)
            #pragma unroll
            for (int j = 0; j < 4; j++) o[mt][nt][j] = 0.f;

    const int srcA = (lane & ~3) | (tg >> 1);
    const int srcB = srcA + 2;

    for (int t = 0; t < LL / 64; t++) {
        const int buf = t & 1;
        if (t == LL / 64 - 1) asm volatile("cp.async.wait_group 0;");
        else                  asm volatile("cp.async.wait_group 1;");
        __syncthreads();

        const unsigned kB = kBase + buf * FK_WORDS * 4;
        const unsigned vB = vBase + buf * FV_WORDS * 4;

        // S = Q @ K^T  (warp: 32 x 64)
        float s[2][8][4];
        #pragma unroll
        for (int mt = 0; mt < 2; mt++)
            #pragma unroll
            for (int nt = 0; nt < 8; nt++)
                #pragma unroll
                for (int j = 0; j < 4; j++) s[mt][nt][j] = 0.f;
        #pragma unroll
        for (int kg = 0; kg < 8; kg++) {
            unsigned qf[2][4];
            #pragma unroll
            for (int mt = 0; mt < 2; mt++) {
                int row = mW + mt * 16 + (sub & 1) * 8 + rr;
                int cl  = 2 * kg + (sub >> 1);
                ldsm4(qf[mt], qBase + ((row * 16 + ((cl & 8) | ((cl ^ row) & 7))) << 4));
            }
            unsigned kf[4][4];
            #pragma unroll
            for (int p = 0; p < 4; p++) {
                int row = 16 * p + (sub >> 1) * 8 + rr;
                int cl  = 2 * kg + (sub & 1);
                ldsm4(kf[p], kB + ((row * 16 + ((cl & 8) | ((cl ^ row) & 7))) << 4));
            }
            #pragma unroll
            for (int mt = 0; mt < 2; mt++)
                #pragma unroll
                for (int nt = 0; nt < 8; nt++)
                    mma_tf32(s[mt][nt], qf[mt],
                             kf[nt >> 1][(nt & 1) * 2], kf[nt >> 1][(nt & 1) * 2 + 1]);
        }

        // scale + mask + online softmax (4 row-groups per lane)
        const int key0 = t * 64;
        float rm[2][2];
        rm[0][0] = rm[0][1] = rm[1][0] = rm[1][1] = -INFINITY;
        #pragma unroll
        for (int mt = 0; mt < 2; mt++)
            #pragma unroll
            for (int nt = 0; nt < 8; nt++) {
                float ma = Ms[key0 + 8 * nt + 2 * tg];
                float mb = Ms[key0 + 8 * nt + 2 * tg + 1];
                s[mt][nt][0] = s[mt][nt][0] * 0.125f + ma;
                s[mt][nt][1] = s[mt][nt][1] * 0.125f + mb;
                s[mt][nt][2] = s[mt][nt][2] * 0.125f + ma;
                s[mt][nt][3] = s[mt][nt][3] * 0.125f + mb;
                rm[mt][0] = fmaxf(rm[mt][0], fmaxf(s[mt][nt][0], s[mt][nt][1]));
                rm[mt][1] = fmaxf(rm[mt][1], fmaxf(s[mt][nt][2], s[mt][nt][3]));
            }
        #pragma unroll
        for (int mt = 0; mt < 2; mt++)
            #pragma unroll
            for (int hf = 0; hf < 2; hf++) {
                float v = rm[mt][hf];
                v = fmaxf(v, __shfl_xor_sync(0xffffffffu, v, 1));
                v = fmaxf(v, __shfl_xor_sync(0xffffffffu, v, 2));
                rm[mt][hf] = v;
            }

        float al[2][2], sum[2][2];
        #pragma unroll
        for (int mt = 0; mt < 2; mt++)
            #pragma unroll
            for (int hf = 0; hf < 2; hf++) {
                float mn = fmaxf(m[mt][hf], rm[mt][hf]);
                al[mt][hf] = __expf(m[mt][hf] - mn);
                m[mt][hf] = mn;
                sum[mt][hf] = 0.f;
            }
        #pragma unroll
        for (int mt = 0; mt < 2; mt++)
            #pragma unroll
            for (int nt = 0; nt < 8; nt++) {
                s[mt][nt][0] = __expf(s[mt][nt][0] - m[mt][0]);
                s[mt][nt][1] = __expf(s[mt][nt][1] - m[mt][0]);
                s[mt][nt][2] = __expf(s[mt][nt][2] - m[mt][1]);
                s[mt][nt][3] = __expf(s[mt][nt][3] - m[mt][1]);
                sum[mt][0] += s[mt][nt][0] + s[mt][nt][1];
                sum[mt][1] += s[mt][nt][2] + s[mt][nt][3];
            }
        #pragma unroll
        for (int mt = 0; mt < 2; mt++)
            #pragma unroll
            for (int hf = 0; hf < 2; hf++) {
                float v = sum[mt][hf];
                v += __shfl_xor_sync(0xffffffffu, v, 1);
                v += __shfl_xor_sync(0xffffffffu, v, 2);
                l[mt][hf] = l[mt][hf] * al[mt][hf] + v;
            }
        #pragma unroll
        for (int mt = 0; mt < 2; mt++)
            #pragma unroll
            for (int nt = 0; nt < 8; nt++) {
                o[mt][nt][0] *= al[mt][0]; o[mt][nt][1] *= al[mt][0];
                o[mt][nt][2] *= al[mt][1]; o[mt][nt][3] *= al[mt][1];
            }

        // O += P @ V : V^T fragments via ldmatrix; P shuffled into A layout
        #pragma unroll
        for (int kg = 0; kg < 8; kg++) {
            unsigned vf[4][4];
            #pragma unroll
            for (int p = 0; p < 4; p++) {
                int row = 16 * p + (sub >> 1) * 8 + rr;
                int cl  = 2 * kg + (sub & 1);
                ldsm4(vf[p], vB + ((row * 16 + ((cl & 8) | ((cl ^ row) & 7))) << 4));
            }
            #pragma unroll
            for (int mt = 0; mt < 2; mt++) {
                float w0, w1;
                unsigned a[4];
                w0 = __shfl_sync(0xffffffffu, s[mt][kg][0], srcA);
                w1 = __shfl_sync(0xffffffffu, s[mt][kg][1], srcA);
                a[0] = __float_as_uint((tg & 1) ? w1 : w0);
                w0 = __shfl_sync(0xffffffffu, s[mt][kg][2], srcA);
                w1 = __shfl_sync(0xffffffffu, s[mt][kg][3], srcA);
                a[1] = __float_as_uint((tg & 1) ? w1 : w0);
                w0 = __shfl_sync(0xffffffffu, s[mt][kg][0], srcB);
                w1 = __shfl_sync(0xffffffffu, s[mt][kg][1], srcB);
                a[2] = __float_as_uint((tg & 1) ? w1 : w0);
                w0 = __shfl_sync(0xffffffffu, s[mt][kg][2], srcB);
                w1 = __shfl_sync(0xffffffffu, s[mt][kg][3], srcB);
                a[3] = __float_as_uint((tg & 1) ? w1 : w0);
                #pragma unroll
                for (int nt = 0; nt < 8; nt++)
                    mma_tf32(o[mt][nt], a,
                             vf[nt >> 1][(nt & 1) * 2], vf[nt >> 1][(nt & 1) * 2 + 1]);
            }
        }
        __syncthreads();
        if (t + 2 < LL / 64) loadKV(t + 2, buf);
    }

    // normalize + write ctx
    float* cb = ctx + ((size_t)b * LL + q0 + mW) * DD + h * DHH;
    #pragma unroll
    for (int mt = 0; mt < 2; mt++) {
        float i0 = 1.f / l[mt][0], i1 = 1.f / l[mt][1];
        #pragma unroll
        for (int nt = 0; nt < 8; nt++) {
            int c = 8 * nt + 2 * tg;
            float2 u0, u1;
            u0.x = o[mt][nt][0] * i0; u0.y = o[mt][nt][1] * i0;
            u1.x = o[mt][nt][2] * i1; u1.y = o[mt][nt][3] * i1;
            *(float2*)(cb + (size_t)(mt * 16 + g) * DD + c) = u0;
            *(float2*)(cb + (size_t)(mt * 16 + g + 8) * DD + c) = u1;
        }
    }
}

// ---------------------------------------------------------------------------
extern "C" void kernel_launch(void* const* d_in, const int* in_sizes, int n_in,
                              void* d_out, int out_size) {
    (void)in_sizes; (void)n_in; (void)out_size;
    const float* x_in  = (const float*)d_in[0];
    const unsigned char* mask = (const unsigned char*)d_in[1];
    const float* ln_ag = (const float*)d_in[2];
    const float* ln_ab = (const float*)d_in[3];
    const float* wq = (const float*)d_in[4];
    const float* bq = (const float*)d_in[5];
    const float* wk = (const float*)d_in[6];
    const float* bk = (const float*)d_in[7];
    const float* wv = (const float*)d_in[8];
    const float* bv = (const float*)d_in[9];
    const float* wo = (const float*)d_in[10];
    const float* bo = (const float*)d_in[11];
    const float* ln_fg = (const float*)d_in[12];
    const float* ln_fb = (const float*)d_in[13];
    const float* w1 = (const float*)d_in[14];
    const float* b1 = (const float*)d_in[15];
    const float* w2 = (const float*)d_in[16];
    const float* b2 = (const float*)d_in[17];

    float* x = (float*)d_out;   // residual stream lives in the output buffer

    float *ph, *pqkv, *pvT, *pctx, *pffn, *pqkvT, *poT, *pw1T, *pw2T, *pbqkv;
    cudaGetSymbolAddress((void**)&ph,    g_h);
    cudaGetSymbolAddress((void**)&pqkv,  g_qkv);
    cudaGetSymbolAddress((void**)&pvT,   g_vT);
    cudaGetSymbolAddress((void**)&pctx,  g_ctx);
    cudaGetSymbolAddress((void**)&pffn,  g_ffn);
    cudaGetSymbolAddress((void**)&pqkvT, g_qkvT);
    cudaGetSymbolAddress((void**)&poT,   g_oT);
    cudaGetSymbolAddress((void**)&pw1T,  g_w1T);
    cudaGetSymbolAddress((void**)&pw2T,  g_w2T);
    cudaGetSymbolAddress((void**)&pbqkv, g_bqkv);

    cudaFuncSetAttribute(flash_kernel,
                         cudaFuncAttributeMaxDynamicSharedMemorySize, FLASH_SMEM);
    cudaFuncSetAttribute(mma_gemm<0,0>,
                         cudaFuncAttributeMaxDynamicSharedMemorySize, GEMM_SMEM);
    cudaFuncSetAttribute(mma_gemm<0,1>,
                         cudaFuncAttributeMaxDynamicSharedMemorySize, GEMM_SMEM);
    cudaFuncSetAttribute(mma_gemm<1,0>,
                         cudaFuncAttributeMaxDynamicSharedMemorySize, GEMM_SMEM);

    cudaMemcpyAsync(x, x_in, (size_t)MTOT * DD * sizeof(float),
                    cudaMemcpyDeviceToDevice, 0);

    // ---- fused prep: all weight transposes + bias packing, one launch ----
    prep_kernel<<<PREP_BLOCKS, 256>>>(wq, wk, wv, wo, w1, w2, bq, bk, bv,
                                      pqkvT, poT, pw1T, pw2T, pbqkv);

    dim3 blk(256);
    dim3 gqkv(D3 / 128, MTOT / 128);  // (12, 32)
    dim3 gp(DD / 128, MTOT / 128);    // (4, 32)
    dim3 g1(D2 / 128, MTOT / 128);    // (8, 32)
    dim3 gfl(LL / 128, BB * HH);      // (16, 16)
    dim3 gvt(LL / 32, DD / 32, BB);   // (64, 16, 2)

    for (int l = 0; l < NLAYERS; l++) {
        // ---- attention block ----
        ln_kernel<<<MTOT, blk>>>(x, ln_ag + l * DD, ln_ab + l * DD, ph);
        mma_gemm<0,0><<<gqkv, blk, GEMM_SMEM>>>(
            ph, DD, pqkvT + (size_t)l * D3 * DD, DD, pbqkv + l * D3,
            nullptr, pqkv, D3, DD);
        vtrans_kernel<<<gvt, blk>>>(pqkv, pvT);
        flash_kernel<<<gfl, dim3(128), FLASH_SMEM>>>(pqkv, pvT, mask, pctx);
        mma_gemm<0,1><<<gp, blk, GEMM_SMEM>>>(
            pctx, DD, poT + (size_t)l * DD * DD, DD, bo + l * DD, x, x, DD, DD);

        // ---- FFN block ----
        ln_kernel<<<MTOT, blk>>>(x, ln_fg + l * DD, ln_fb + l * DD, ph);
        mma_gemm<1,0><<<g1, blk, GEMM_SMEM>>>(
            ph, DD, pw1T + (size_t)l * D2 * DD, DD, b1 + l * D2,
            nullptr, pffn, D2, DD);
        mma_gemm<0,1><<<gp, blk, GEMM_SMEM>>>(
            pffn, D2, pw2T + (size_t)l * DD * D2, D2, b2 + l * DD, x, x, DD, D2);
    }
}